// round 10
// baseline (speedup 1.0000x reference)
#include <cuda_runtime.h>
#include <cuda_fp16.h>
#include <math.h>
#include <stdint.h>

// ---------------- problem constants ----------------
#define HHs   56
#define NTOK  100352
#define WN    49
#define NC_A  6      // K=384  -> 6 chunks of 64
#define NC_H  24     // K=1536 -> 24 chunks of 64

// ---------------- scratch: chunk-major, pre-swizzled fp16 layouts ----------------
__device__ __align__(1024) __half g_act [(size_t)NC_A * NTOK * 64];   // LN1 / attn out (window order)
__device__ __align__(1024) __half g_act2[(size_t)NC_A * NTOK * 64];   // LN2 out (sequence order)
__device__ __align__(1024) __half g_hid [(size_t)NC_H * NTOK * 64];
__device__ __align__(256) __half g_qkv [(size_t)NTOK * 1152];         // fp16 row-major
__device__ __align__(256) float  g_xres[(size_t)NTOK * 384];
// weights: [NC chunks][N][64] single fp16
__device__ __align__(1024) __half g_wq[(size_t)NC_A * 1152 * 64];
__device__ __align__(1024) __half g_wp[(size_t)NC_A *  384 * 64];
__device__ __align__(1024) __half g_w1[(size_t)NC_A * 1536 * 64];
__device__ __align__(1024) __half g_w2[(size_t)NC_H *  384 * 64];

// ---------------- PTX helpers ----------------
__device__ __forceinline__ uint32_t smem_u32(const void* p) {
    uint32_t a;
    asm("{ .reg .u64 t; cvta.to.shared.u64 t, %1; cvt.u32.u64 %0, t; }" : "=r"(a) : "l"(p));
    return a;
}
#define MBARRIER_INIT(mb, c) \
    asm volatile("mbarrier.init.shared.b64 [%0], %1;" :: "r"((uint32_t)(mb)), "r"((uint32_t)(c)) : "memory")
#define MBARRIER_EXPECT_TX(mb, n) \
    asm volatile("mbarrier.arrive.expect_tx.shared.b64 _, [%0], %1;" :: "r"((uint32_t)(mb)), "r"((uint32_t)(n)) : "memory")
#define MBARRIER_WAIT_PARITY(mb, par) do { \
    uint32_t _m = (uint32_t)(mb), _p = (uint32_t)(par), _d; \
    asm volatile("{\n\t.reg .pred p;\n\t" \
        "mbarrier.try_wait.parity.acquire.cta.shared::cta.b64 p, [%1], %2;\n\t" \
        "selp.b32 %0, 1, 0, p;\n\t}" : "=r"(_d) : "r"(_m), "r"(_p) : "memory"); \
    if (!_d) { \
        asm volatile("{\n\t.reg .pred P1;\n\t" \
            "WL_%=:\n\t" \
            "mbarrier.try_wait.parity.acquire.cta.shared::cta.b64 P1, [%0], %1, 0x989680;\n\t" \
            "@P1 bra.uni WD_%=;\n\t" \
            "bra.uni WL_%=;\n\t" \
            "WD_%=:\n\t}" :: "r"(_m), "r"(_p) : "memory"); \
    } } while (0)
#define BULK_G2S(dst, src, n, mb) \
    asm volatile("cp.async.bulk.shared::cluster.global.mbarrier::complete_tx::bytes [%0], [%1], %2, [%3];" \
        :: "r"((uint32_t)(dst)), "l"(src), "r"((uint32_t)(n)), "r"((uint32_t)(mb)) : "memory")
#define FENCE_ASYNC() asm volatile("fence.proxy.async.shared::cta;" ::: "memory")
#define LDSM_X4(r0, r1, r2, r3, addr) \
    asm volatile("ldmatrix.sync.aligned.m8n8.x4.shared.b16 {%0,%1,%2,%3}, [%4];" \
                 : "=r"(r0), "=r"(r1), "=r"(r2), "=r"(r3) : "r"(addr))

__device__ __forceinline__ void mma16816(float* c, const uint32_t* a, const uint32_t* b) {
    asm volatile("mma.sync.aligned.m16n8k16.row.col.f32.f16.f16.f32 "
        "{%0,%1,%2,%3}, {%4,%5,%6,%7}, {%8,%9}, {%0,%1,%2,%3};"
        : "+f"(c[0]), "+f"(c[1]), "+f"(c[2]), "+f"(c[3])
        : "r"(a[0]), "r"(a[1]), "r"(a[2]), "r"(a[3]), "r"(b[0]), "r"(b[1]));
}

// window-order row -> sequence row (roll map; same both directions)
__device__ __forceinline__ int win_to_seq(int r) {
    int n  = r % WN;
    int t  = r / WN;
    int wc = t & 7, wr = (t >> 3) & 7, b = t >> 6;
    int n7 = n / 7;
    int h = wr * 7 + n7, w = wc * 7 + (n - n7 * 7);
    int dh = h + 3; if (dh >= HHs) dh -= HHs;
    int dw = w + 3; if (dw >= HHs) dw -= HHs;
    return (b * HHs + dh) * HHs + dw;
}

// fp16 store of 2 adjacent cols into chunk-major swizzled layout (k even)
__device__ __forceinline__ void h_store2(__half* base, int rows, int tok, int k,
                                         float v0, float v1) {
    int ch  = k >> 6;
    int idx = ((((k >> 3) & 7) ^ (tok & 7)) << 3) + (k & 7);
    *(__half2*)(base + ((size_t)ch * rows + tok) * 64 + idx) = __floats2half2_rn(v0, v1);
}

// ---------------- weight prep: W[K][N] fp32 -> [NC][N][64] swizzled fp16 ----------------
__global__ void wprep(const float* __restrict__ W, int K, int N, __half* __restrict__ O)
{
    __shared__ float t[32][33];
    int nb = blockIdx.x * 32, kb = blockIdx.y * 32;
    for (int i = threadIdx.y; i < 32; i += 8)
        t[i][threadIdx.x] = W[(size_t)(kb + i) * N + nb + threadIdx.x];
    __syncthreads();
    for (int i = threadIdx.y; i < 32; i += 8) {
        float v = t[threadIdx.x][i];
        int k = kb + threadIdx.x, n = nb + i;
        int ch  = k >> 6;
        int idx = ((((k >> 3) & 7) ^ (n & 7)) << 3) + (k & 7);
        O[((size_t)ch * N + n) * 64 + idx] = __float2half_rn(v);
    }
}

// ---------------- LayerNorm1 -> chunked fp16 (one warp per token, rolled gather) ----------------
__global__ void ln_kernel(const float* __restrict__ X, const float* __restrict__ G,
                          const float* __restrict__ Bv, __half* __restrict__ Y)
{
    int gw   = (blockIdx.x * blockDim.x + threadIdx.x) >> 5;
    int lane = threadIdx.x & 31;
    if (gw >= NTOK) return;
    int src = win_to_seq(gw);
    const float4* xr = (const float4*)(X + (size_t)src * 384);
    float4 a = xr[lane], b = xr[32 + lane], c = xr[64 + lane];
    float s = a.x+a.y+a.z+a.w + b.x+b.y+b.z+b.w + c.x+c.y+c.z+c.w;
    float q = a.x*a.x+a.y*a.y+a.z*a.z+a.w*a.w
            + b.x*b.x+b.y*b.y+b.z*b.z+b.w*b.w
            + c.x*c.x+c.y*c.y+c.z*c.z+c.w*c.w;
    #pragma unroll
    for (int o = 16; o; o >>= 1) {
        s += __shfl_xor_sync(0xffffffffu, s, o);
        q += __shfl_xor_sync(0xffffffffu, q, o);
    }
    float mu  = s * (1.0f / 384.0f);
    float var = q * (1.0f / 384.0f) - mu * mu;
    float rs  = rsqrtf(var + 1e-5f);
    const float4* gg = (const float4*)G;
    const float4* bb = (const float4*)Bv;
    #pragma unroll
    for (int seg = 0; seg < 3; seg++) {
        float4 v  = (seg == 0) ? a : (seg == 1) ? b : c;
        float4 g4 = gg[seg * 32 + lane];
        float4 b4 = bb[seg * 32 + lane];
        int k0 = seg * 128 + lane * 4;
        float w0 = (v.x - mu) * rs * g4.x + b4.x;
        float w1 = (v.y - mu) * rs * g4.y + b4.y;
        float w2 = (v.z - mu) * rs * g4.z + b4.z;
        float w3 = (v.w - mu) * rs * g4.w + b4.w;
        h_store2(Y, NTOK, gw, k0,     w0, w1);
        h_store2(Y, NTOK, gw, k0 + 2, w2, w3);
    }
}

// ---------------- attention: fp16 qkv in, float4-vectorized smem k/v ----------------
__global__ __launch_bounds__(64)
void attn_kernel(const __half* __restrict__ qkv, __half* __restrict__ O)
{
    __shared__ float4 kk[WN * 8], vv[WN * 8];
    int win = blockIdx.x, head = blockIdx.y;
    int t = threadIdx.x;
    const __half* base = qkv + (size_t)win * WN * 1152 + head * 32;
    for (int u = t; u < WN * 8; u += 64) {
        int m = u >> 3, j = u & 7;
        const __half2* kp = (const __half2*)(base + (size_t)m * 1152 + 384 + j * 4);
        const __half2* vp = (const __half2*)(base + (size_t)m * 1152 + 768 + j * 4);
        float2 k0 = __half22float2(kp[0]), k1 = __half22float2(kp[1]);
        float2 v0 = __half22float2(vp[0]), v1 = __half22float2(vp[1]);
        kk[u] = make_float4(k0.x, k0.y, k1.x, k1.y);
        vv[u] = make_float4(v0.x, v0.y, v1.x, v1.y);
    }
    __syncthreads();
    if (t >= WN) return;
    float q[32];
    const __half2* qr = (const __half2*)(base + (size_t)t * 1152);
    #pragma unroll
    for (int j = 0; j < 16; j++) {
        float2 f = __half22float2(qr[j]);
        q[2*j] = f.x; q[2*j+1] = f.y;
    }
    float s[WN];
    #pragma unroll
    for (int m = 0; m < WN; m++) {
        float a = 0.0f;
        #pragma unroll
        for (int j = 0; j < 8; j++) {
            float4 f = kk[m*8 + j];
            a += q[4*j]*f.x + q[4*j+1]*f.y + q[4*j+2]*f.z + q[4*j+3]*f.w;
        }
        s[m] = a * 0.17677669529663687f;
    }
    float mx = -1e30f;
    #pragma unroll
    for (int m = 0; m < WN; m++) mx = fmaxf(mx, s[m]);
    float sum = 0.0f;
    #pragma unroll
    for (int m = 0; m < WN; m++) { s[m] = __expf(s[m] - mx); sum += s[m]; }
    float inv = 1.0f / sum;
    float o[32];
    #pragma unroll
    for (int j = 0; j < 32; j++) o[j] = 0.0f;
    #pragma unroll
    for (int m = 0; m < WN; m++) {
        float w = s[m] * inv;
        #pragma unroll
        for (int j = 0; j < 8; j++) {
            float4 f = vv[m*8 + j];
            o[4*j] += w*f.x; o[4*j+1] += w*f.y; o[4*j+2] += w*f.z; o[4*j+3] += w*f.w;
        }
    }
    int tok = win * WN + t;
    int k0 = head * 32;
    #pragma unroll
    for (int j = 0; j < 32; j += 2)
        h_store2(O, NTOK, tok, k0 + j, o[j], o[j + 1]);
}

// ---------------- generic fp16 GEMM: 128x128 CTA, 3 stages ----------------
#define STAGES 3
#define STG_BYTES 32768
#define MBAR_OFF  98304
#define SMEM_DYN  (98304 + 64)

// EPI 0: qkv fp16   1: gelu -> chunked fp16   3: resid fp32
template<int EPI>
__global__ __launch_bounds__(256)
void gemm_mma(const __half* __restrict__ A, const __half* __restrict__ B,
              const float* __restrict__ bias, float* __restrict__ Co,
              __half* __restrict__ O2, const float* __restrict__ resid,
              int NC, int Nn)
{
    extern __shared__ __align__(1024) char sm[];
    uint32_t sb = smem_u32(sm);
    int tid = threadIdx.x, lane = tid & 31, wid = tid >> 5;
    int wm = wid & 1, wn = wid >> 1;           // 2(M) x 4(N) warps, warp tile 64x32
    int m0 = blockIdx.y * 128, n0 = blockIdx.x * 128;

    if (tid == 0) {
        #pragma unroll
        for (int s = 0; s < STAGES; s++) MBARRIER_INIT(sb + MBAR_OFF + s * 8, 1);
        FENCE_ASYNC();
    }
    __syncthreads();

    auto issue = [&](int j) {
        const char* asrc = (const char*)A + ((size_t)j * NTOK + m0) * 128;
        const char* bsrc = (const char*)B + ((size_t)j * Nn   + n0) * 128;
        int s = j % STAGES;
        uint32_t dst = sb + s * STG_BYTES;
        uint32_t mb  = sb + MBAR_OFF + s * 8;
        MBARRIER_EXPECT_TX(mb, 32768);
        BULK_G2S(dst,         asrc, 16384, mb);
        BULK_G2S(dst + 16384, bsrc, 16384, mb);
    };
    if (tid == 0) { issue(0); issue(1); issue(2); }

    float acc[4][4][4];
    #pragma unroll
    for (int i = 0; i < 4; i++)
        #pragma unroll
        for (int j = 0; j < 4; j++)
            #pragma unroll
            for (int u = 0; u < 4; u++) acc[i][j][u] = 0.0f;

    for (int i = 0; i < NC; i++) {
        int s = i % STAGES;
        MBARRIER_WAIT_PARITY(sb + MBAR_OFF + s * 8, (i / STAGES) & 1);

        uint32_t As = sb + s * STG_BYTES;
        uint32_t Bs = As + 16384;
        #pragma unroll
        for (int kk = 0; kk < 4; kk++) {
            int ch = kk * 2 + (lane >> 4);
            uint32_t b[4][2];
            #pragma unroll
            for (int j2 = 0; j2 < 2; j2++) {
                int row = wn * 32 + j2 * 16 + (lane & 15);
                uint32_t r0, r1, r2, r3;
                LDSM_X4(r0, r1, r2, r3,
                        Bs + (uint32_t)row * 128 + (uint32_t)((ch ^ (row & 7)) << 4));
                b[2*j2][0] = r0; b[2*j2][1] = r2;
                b[2*j2+1][0] = r1; b[2*j2+1][1] = r3;
            }
            #pragma unroll
            for (int ii = 0; ii < 4; ii++) {
                int row = wm * 64 + ii * 16 + (lane & 15);
                uint32_t a[4];
                LDSM_X4(a[0], a[1], a[2], a[3],
                        As + (uint32_t)row * 128 + (uint32_t)((ch ^ (row & 7)) << 4));
                #pragma unroll
                for (int j = 0; j < 4; j++) mma16816(acc[ii][j], a, b[j]);
            }
        }
        __syncthreads();
        if (tid == 0 && i + STAGES < NC) issue(i + STAGES);
    }

    // stage C through smem (fp32, stride 132)
    float* smf = (float*)sm;
    #pragma unroll
    for (int i = 0; i < 4; i++)
        #pragma unroll
        for (int j = 0; j < 4; j++) {
            int br = wm * 64 + i * 16 + (lane >> 2);
            int bc = wn * 32 + j * 8 + 2 * (lane & 3);
            *(float2*)&smf[br * 132 + bc]       = make_float2(acc[i][j][0], acc[i][j][1]);
            *(float2*)&smf[(br + 8) * 132 + bc] = make_float2(acc[i][j][2], acc[i][j][3]);
        }
    __syncthreads();

    int r    = tid >> 1;
    int cb0  = (tid & 1) * 64;
    int grow = m0 + r;
    const float* srow = &smf[r * 132 + cb0];
    if (EPI == 0) {
        __half* dst = O2 + (size_t)grow * Nn + n0 + cb0;
        #pragma unroll
        for (int c = 0; c < 64; c += 2) {
            float v0 = srow[c]   + bias[n0+cb0+c];
            float v1 = srow[c+1] + bias[n0+cb0+c+1];
            *(__half2*)(dst + c) = __floats2half2_rn(v0, v1);
        }
    } else if (EPI == 1) {
        int gc0 = n0 + cb0;
        int ch  = gc0 >> 6;
        __half* hp = O2 + ((size_t)ch * NTOK + grow) * 64;
        #pragma unroll
        for (int c = 0; c < 64; c += 2) {
            float v0 = srow[c]   + bias[gc0 + c];
            float v1 = srow[c+1] + bias[gc0 + c + 1];
            v0 = 0.5f * v0 * (1.0f + erff(v0 * 0.70710678118654752f));
            v1 = 0.5f * v1 * (1.0f + erff(v1 * 0.70710678118654752f));
            int idx = ((((c >> 3) & 7) ^ (grow & 7)) << 3) + (c & 7);
            *(__half2*)(hp + idx) = __floats2half2_rn(v0, v1);
        }
    } else {
        size_t orow = (size_t)grow * Nn;
        float* dst = Co + orow + n0 + cb0;
        const float* rp = resid + orow + n0 + cb0;
        #pragma unroll
        for (int c = 0; c < 64; c += 4) {
            float4 rr = *(const float4*)(rp + c);
            float4 o;
            o.x = srow[c+0] + bias[n0+cb0+c+0] + rr.x;
            o.y = srow[c+1] + bias[n0+cb0+c+1] + rr.y;
            o.z = srow[c+2] + bias[n0+cb0+c+2] + rr.z;
            o.w = srow[c+3] + bias[n0+cb0+c+3] + rr.w;
            *(float4*)(dst + c) = o;
        }
    }
}

// ---------------- proj GEMM 128x384 + scatter + residual + fused LN2 ----------------
// stage = A 16KB + B 48KB = 64KB, 2 stages; C staged 128x388 fp32 (reuses stage smem)
#define P_STG   65536
#define P_MBAR  198656                  // after C region (128*388*4 = 198656)
#define P_SMEM  (198656 + 64)

__global__ __launch_bounds__(256)
void gemm_proj_ln(const __half* __restrict__ A, const __half* __restrict__ B,
                  const float* __restrict__ bias, const float* __restrict__ x,
                  const float* __restrict__ G, const float* __restrict__ Bv,
                  float* __restrict__ xres, __half* __restrict__ actout)
{
    extern __shared__ __align__(1024) char sm[];
    uint32_t sb = smem_u32(sm);
    int tid = threadIdx.x, lane = tid & 31, wid = tid >> 5;
    int wm = wid & 1, wn = wid >> 1;           // 2(M) x 4(N), warp tile 64x96
    int m0 = blockIdx.x * 128;

    if (tid == 0) {
        MBARRIER_INIT(sb + P_MBAR,     1);
        MBARRIER_INIT(sb + P_MBAR + 8, 1);
        FENCE_ASYNC();
    }
    __syncthreads();

    auto issue = [&](int j) {
        const char* asrc = (const char*)A + ((size_t)j * NTOK + m0) * 128;
        const char* bsrc = (const char*)B + (size_t)j * 384 * 128;
        int s = j & 1;
        uint32_t dst = sb + s * P_STG;
        uint32_t mb  = sb + P_MBAR + s * 8;
        MBARRIER_EXPECT_TX(mb, 65536);
        BULK_G2S(dst,         asrc, 16384, mb);
        BULK_G2S(dst + 16384, bsrc, 49152, mb);
    };
    if (tid == 0) { issue(0); issue(1); }

    float acc[4][12][4];
    #pragma unroll
    for (int i = 0; i < 4; i++)
        #pragma unroll
        for (int j = 0; j < 12; j++)
            #pragma unroll
            for (int u = 0; u < 4; u++) acc[i][j][u] = 0.0f;

    for (int i = 0; i < NC_A; i++) {
        int s = i & 1;
        MBARRIER_WAIT_PARITY(sb + P_MBAR + s * 8, (i >> 1) & 1);

        uint32_t As = sb + s * P_STG;
        uint32_t Bs = As + 16384;
        #pragma unroll
        for (int kk = 0; kk < 4; kk++) {
            int ch = kk * 2 + (lane >> 4);
            uint32_t b[12][2];
            #pragma unroll
            for (int j2 = 0; j2 < 6; j2++) {
                int row = wn * 96 + j2 * 16 + (lane & 15);
                uint32_t r0, r1, r2, r3;
                LDSM_X4(r0, r1, r2, r3,
                        Bs + (uint32_t)row * 128 + (uint32_t)((ch ^ (row & 7)) << 4));
                b[2*j2][0] = r0; b[2*j2][1] = r2;
                b[2*j2+1][0] = r1; b[2*j2+1][1] = r3;
            }
            #pragma unroll
            for (int ii = 0; ii < 4; ii++) {
                int row = wm * 64 + ii * 16 + (lane & 15);
                uint32_t a[4];
                LDSM_X4(a[0], a[1], a[2], a[3],
                        As + (uint32_t)row * 128 + (uint32_t)((ch ^ (row & 7)) << 4));
                #pragma unroll
                for (int j = 0; j < 12; j++) mma16816(acc[ii][j], a, b[j]);
            }
        }
        __syncthreads();
        if (tid == 0 && i + 2 < NC_A) issue(i + 2);
    }

    // stage full 128x384 C into smem (stride 388)
    float* smf = (float*)sm;
    #pragma unroll
    for (int i = 0; i < 4; i++)
        #pragma unroll
        for (int j = 0; j < 12; j++) {
            int br = wm * 64 + i * 16 + (lane >> 2);
            int bc = wn * 96 + j * 8 + 2 * (lane & 3);
            *(float2*)&smf[br * 388 + bc]       = make_float2(acc[i][j][0], acc[i][j][1]);
            *(float2*)&smf[(br + 8) * 388 + bc] = make_float2(acc[i][j][2], acc[i][j][3]);
        }
    __syncthreads();

    // fused: xres = x + bias + C (scattered), then LN over the 384-row -> act2 (SEQ order)
    int r    = tid >> 1;
    int half = tid & 1;                 // cols half*192 .. +191
    int c0   = half * 192;
    int tok  = m0 + r;                  // window-order token
    int seqr = win_to_seq(tok);
    float* vrow = &smf[r * 388 + c0];
    const float* xp = x + (size_t)seqr * 384 + c0;
    float* xo = xres + (size_t)seqr * 384 + c0;
    float s = 0.0f, q = 0.0f;
    #pragma unroll
    for (int c = 0; c < 192; c += 4) {
        float4 xr4 = *(const float4*)(xp + c);
        float4 b4  = *(const float4*)(bias + c0 + c);
        float4 v;
        v.x = vrow[c+0] + b4.x + xr4.x;
        v.y = vrow[c+1] + b4.y + xr4.y;
        v.z = vrow[c+2] + b4.z + xr4.z;
        v.w = vrow[c+3] + b4.w + xr4.w;
        *(float4*)(vrow + c) = v;
        *(float4*)(xo + c)   = v;
        s += v.x + v.y + v.z + v.w;
        q += v.x*v.x + v.y*v.y + v.z*v.z + v.w*v.w;
    }
    s += __shfl_xor_sync(0xffffffffu, s, 1);
    q += __shfl_xor_sync(0xffffffffu, q, 1);
    float mu  = s * (1.0f / 384.0f);
    float var = q * (1.0f / 384.0f) - mu * mu;
    float rs  = rsqrtf(var + 1e-5f);
    #pragma unroll
    for (int c = 0; c < 192; c += 2) {
        int k = c0 + c;
        float g0 = G[k], g1 = G[k+1], p0 = Bv[k], p1 = Bv[k+1];
        float w0 = (vrow[c]   - mu) * rs * g0 + p0;
        float w1 = (vrow[c+1] - mu) * rs * g1 + p1;
        h_store2(actout, NTOK, seqr, k, w0, w1);   // separate buffer, no alias race
    }
}

// ---------------- launcher ----------------
extern "C" void kernel_launch(void* const* d_in, const int* in_sizes, int n_in,
                              void* d_out, int out_size)
{
    const float* x      = (const float*)d_in[0];
    const float* ln1_g  = (const float*)d_in[1];
    const float* ln1_b  = (const float*)d_in[2];
    const float* w_qkv  = (const float*)d_in[3];
    const float* b_qkv  = (const float*)d_in[4];
    const float* w_proj = (const float*)d_in[5];
    const float* b_proj = (const float*)d_in[6];
    const float* ln2_g  = (const float*)d_in[7];
    const float* ln2_b  = (const float*)d_in[8];
    const float* w_fc1  = (const float*)d_in[9];
    const float* b_fc1  = (const float*)d_in[10];
    const float* w_fc2  = (const float*)d_in[11];
    const float* b_fc2  = (const float*)d_in[12];
    float* out = (float*)d_out;

    __half *act, *act2, *hid, *qkv, *wq, *wp, *w1, *w2;
    float *xres;
    cudaGetSymbolAddress((void**)&act,  g_act);
    cudaGetSymbolAddress((void**)&act2, g_act2);
    cudaGetSymbolAddress((void**)&hid,  g_hid);
    cudaGetSymbolAddress((void**)&qkv,  g_qkv);
    cudaGetSymbolAddress((void**)&xres, g_xres);
    cudaGetSymbolAddress((void**)&wq,   g_wq);
    cudaGetSymbolAddress((void**)&wp,   g_wp);
    cudaGetSymbolAddress((void**)&w1,   g_w1);
    cudaGetSymbolAddress((void**)&w2,   g_w2);

    cudaFuncSetAttribute(gemm_mma<0>, cudaFuncAttributeMaxDynamicSharedMemorySize, SMEM_DYN);
    cudaFuncSetAttribute(gemm_mma<1>, cudaFuncAttributeMaxDynamicSharedMemorySize, SMEM_DYN);
    cudaFuncSetAttribute(gemm_mma<3>, cudaFuncAttributeMaxDynamicSharedMemorySize, SMEM_DYN);
    cudaFuncSetAttribute(gemm_proj_ln, cudaFuncAttributeMaxDynamicSharedMemorySize, P_SMEM);

    // weight prep (single fp16)
    wprep<<<dim3(1152/32,  384/32), dim3(32, 8)>>>(w_qkv,  384,  1152, wq);
    wprep<<<dim3( 384/32,  384/32), dim3(32, 8)>>>(w_proj, 384,   384, wp);
    wprep<<<dim3(1536/32,  384/32), dim3(32, 8)>>>(w_fc1,  384,  1536, w1);
    wprep<<<dim3( 384/32, 1536/32), dim3(32, 8)>>>(w_fc2,  1536,  384, w2);

    const int MT = NTOK / 128;   // 784

    // 1) LN1 + roll + window partition -> act (window order)
    ln_kernel<<<NTOK / 8, 256>>>(x, ln1_g, ln1_b, act);
    // 2) QKV -> fp16
    gemm_mma<0><<<dim3(1152/128, MT), 256, SMEM_DYN>>>(act, wq, b_qkv, nullptr, qkv, nullptr, NC_A, 1152);
    // 3) attention -> act (window order)
    attn_kernel<<<dim3(NTOK / WN, 12), 64>>>(qkv, act);
    // 4) proj + reverse/roll + residual + LN2 -> xres, act2 (sequence order)
    gemm_proj_ln<<<MT, 256, P_SMEM>>>(act, wp, b_proj, x, ln2_g, ln2_b, xres, act2);
    // 5) FC1 + GELU -> hid (sequence order)
    gemm_mma<1><<<dim3(1536/128, MT), 256, SMEM_DYN>>>(act2, w1, b_fc1, nullptr, hid, nullptr, NC_A, 1536);
    // 6) FC2 + residual -> out (sequence order)
    gemm_mma<3><<<dim3( 384/128, MT), 256, SMEM_DYN>>>(hid, w2, b_fc2, out, nullptr, xres, NC_H, 384);
}

// round 11
// speedup vs baseline: 1.0500x; 1.0500x over previous
#include <cuda_runtime.h>
#include <cuda_fp16.h>
#include <math.h>
#include <stdint.h>

// ---------------- problem constants ----------------
#define HHs   56
#define NTOK  100352
#define WN    49
#define NC_A  6      // K=384  -> 6 chunks of 64
#define NC_H  24     // K=1536 -> 24 chunks of 64

// ---------------- scratch: chunk-major, pre-swizzled fp16 layouts ----------------
__device__ __align__(1024) __half g_act[(size_t)NC_A * NTOK * 64];
__device__ __align__(1024) __half g_hid[(size_t)NC_H * NTOK * 64];
__device__ __align__(256) __half g_qkv [(size_t)NTOK * 1152];     // fp16 row-major
__device__ __align__(256) float  g_xres[(size_t)NTOK * 384];
// weights: [NC chunks][N][64] single fp16
__device__ __align__(1024) __half g_wq[(size_t)NC_A * 1152 * 64];
__device__ __align__(1024) __half g_wp[(size_t)NC_A *  384 * 64];
__device__ __align__(1024) __half g_w1[(size_t)NC_A * 1536 * 64];
__device__ __align__(1024) __half g_w2[(size_t)NC_H *  384 * 64];

// ---------------- PTX helpers ----------------
__device__ __forceinline__ uint32_t smem_u32(const void* p) {
    uint32_t a;
    asm("{ .reg .u64 t; cvta.to.shared.u64 t, %1; cvt.u32.u64 %0, t; }" : "=r"(a) : "l"(p));
    return a;
}
#define MBARRIER_INIT(mb, c) \
    asm volatile("mbarrier.init.shared.b64 [%0], %1;" :: "r"((uint32_t)(mb)), "r"((uint32_t)(c)) : "memory")
#define MBARRIER_EXPECT_TX(mb, n) \
    asm volatile("mbarrier.arrive.expect_tx.shared.b64 _, [%0], %1;" :: "r"((uint32_t)(mb)), "r"((uint32_t)(n)) : "memory")
#define MBARRIER_WAIT_PARITY(mb, par) do { \
    uint32_t _m = (uint32_t)(mb), _p = (uint32_t)(par), _d; \
    asm volatile("{\n\t.reg .pred p;\n\t" \
        "mbarrier.try_wait.parity.acquire.cta.shared::cta.b64 p, [%1], %2;\n\t" \
        "selp.b32 %0, 1, 0, p;\n\t}" : "=r"(_d) : "r"(_m), "r"(_p) : "memory"); \
    if (!_d) { \
        asm volatile("{\n\t.reg .pred P1;\n\t" \
            "WL_%=:\n\t" \
            "mbarrier.try_wait.parity.acquire.cta.shared::cta.b64 P1, [%0], %1, 0x989680;\n\t" \
            "@P1 bra.uni WD_%=;\n\t" \
            "bra.uni WL_%=;\n\t" \
            "WD_%=:\n\t}" :: "r"(_m), "r"(_p) : "memory"); \
    } } while (0)
#define BULK_G2S(dst, src, n, mb) \
    asm volatile("cp.async.bulk.shared::cluster.global.mbarrier::complete_tx::bytes [%0], [%1], %2, [%3];" \
        :: "r"((uint32_t)(dst)), "l"(src), "r"((uint32_t)(n)), "r"((uint32_t)(mb)) : "memory")
#define FENCE_ASYNC() asm volatile("fence.proxy.async.shared::cta;" ::: "memory")
#define LDSM_X4(r0, r1, r2, r3, addr) \
    asm volatile("ldmatrix.sync.aligned.m8n8.x4.shared.b16 {%0,%1,%2,%3}, [%4];" \
                 : "=r"(r0), "=r"(r1), "=r"(r2), "=r"(r3) : "r"(addr))

__device__ __forceinline__ void mma16816(float* c, const uint32_t* a, const uint32_t* b) {
    asm volatile("mma.sync.aligned.m16n8k16.row.col.f32.f16.f16.f32 "
        "{%0,%1,%2,%3}, {%4,%5,%6,%7}, {%8,%9}, {%0,%1,%2,%3};"
        : "+f"(c[0]), "+f"(c[1]), "+f"(c[2]), "+f"(c[3])
        : "r"(a[0]), "r"(a[1]), "r"(a[2]), "r"(a[3]), "r"(b[0]), "r"(b[1]));
}

// window-order row -> sequence row (roll map; same both directions)
__device__ __forceinline__ int win_to_seq(int r) {
    int n  = r % WN;
    int t  = r / WN;
    int wc = t & 7, wr = (t >> 3) & 7, b = t >> 6;
    int n7 = n / 7;
    int h = wr * 7 + n7, w = wc * 7 + (n - n7 * 7);
    int dh = h + 3; if (dh >= HHs) dh -= HHs;
    int dw = w + 3; if (dw >= HHs) dw -= HHs;
    return (b * HHs + dh) * HHs + dw;
}

// fp16 store of 2 adjacent cols into chunk-major swizzled layout (k even)
__device__ __forceinline__ void h_store2(__half* base, int rows, int tok, int k,
                                         float v0, float v1) {
    int ch  = k >> 6;
    int idx = ((((k >> 3) & 7) ^ (tok & 7)) << 3) + (k & 7);
    *(__half2*)(base + ((size_t)ch * rows + tok) * 64 + idx) = __floats2half2_rn(v0, v1);
}

// ---------------- weight prep: W[K][N] fp32 -> [NC][N][64] swizzled fp16 ----------------
__global__ void wprep(const float* __restrict__ W, int K, int N, __half* __restrict__ O)
{
    __shared__ float t[32][33];
    int nb = blockIdx.x * 32, kb = blockIdx.y * 32;
    for (int i = threadIdx.y; i < 32; i += 8)
        t[i][threadIdx.x] = W[(size_t)(kb + i) * N + nb + threadIdx.x];
    __syncthreads();
    for (int i = threadIdx.y; i < 32; i += 8) {
        float v = t[threadIdx.x][i];
        int k = kb + threadIdx.x, n = nb + i;
        int ch  = k >> 6;
        int idx = ((((k >> 3) & 7) ^ (n & 7)) << 3) + (k & 7);
        O[((size_t)ch * N + n) * 64 + idx] = __float2half_rn(v);
    }
}

// ---------------- LayerNorm -> chunked fp16 (one warp per token) ----------------
template<bool PERM>
__global__ void ln_kernel(const float* __restrict__ X, const float* __restrict__ G,
                          const float* __restrict__ Bv, __half* __restrict__ Y)
{
    int gw   = (blockIdx.x * blockDim.x + threadIdx.x) >> 5;
    int lane = threadIdx.x & 31;
    if (gw >= NTOK) return;
    int src = PERM ? win_to_seq(gw) : gw;
    const float4* xr = (const float4*)(X + (size_t)src * 384);
    float4 a = xr[lane], b = xr[32 + lane], c = xr[64 + lane];
    float s = a.x+a.y+a.z+a.w + b.x+b.y+b.z+b.w + c.x+c.y+c.z+c.w;
    float q = a.x*a.x+a.y*a.y+a.z*a.z+a.w*a.w
            + b.x*b.x+b.y*b.y+b.z*b.z+b.w*b.w
            + c.x*c.x+c.y*c.y+c.z*c.z+c.w*c.w;
    #pragma unroll
    for (int o = 16; o; o >>= 1) {
        s += __shfl_xor_sync(0xffffffffu, s, o);
        q += __shfl_xor_sync(0xffffffffu, q, o);
    }
    float mu  = s * (1.0f / 384.0f);
    float var = q * (1.0f / 384.0f) - mu * mu;
    float rs  = rsqrtf(var + 1e-5f);
    const float4* gg = (const float4*)G;
    const float4* bb = (const float4*)Bv;
    #pragma unroll
    for (int seg = 0; seg < 3; seg++) {
        float4 v  = (seg == 0) ? a : (seg == 1) ? b : c;
        float4 g4 = gg[seg * 32 + lane];
        float4 b4 = bb[seg * 32 + lane];
        int k0 = seg * 128 + lane * 4;
        float w0 = (v.x - mu) * rs * g4.x + b4.x;
        float w1 = (v.y - mu) * rs * g4.y + b4.y;
        float w2 = (v.z - mu) * rs * g4.z + b4.z;
        float w3 = (v.w - mu) * rs * g4.w + b4.w;
        h_store2(Y, NTOK, gw, k0,     w0, w1);
        h_store2(Y, NTOK, gw, k0 + 2, w2, w3);
    }
}

// ---------------- attention: fp16 qkv in, float4-vectorized smem k/v ----------------
__global__ __launch_bounds__(64)
void attn_kernel(const __half* __restrict__ qkv, __half* __restrict__ O)
{
    __shared__ float4 kk[WN * 8], vv[WN * 8];
    int win = blockIdx.x, head = blockIdx.y;
    int t = threadIdx.x;
    const __half* base = qkv + (size_t)win * WN * 1152 + head * 32;
    for (int u = t; u < WN * 8; u += 64) {
        int m = u >> 3, j = u & 7;
        const __half2* kp = (const __half2*)(base + (size_t)m * 1152 + 384 + j * 4);
        const __half2* vp = (const __half2*)(base + (size_t)m * 1152 + 768 + j * 4);
        float2 k0 = __half22float2(kp[0]), k1 = __half22float2(kp[1]);
        float2 v0 = __half22float2(vp[0]), v1 = __half22float2(vp[1]);
        kk[u] = make_float4(k0.x, k0.y, k1.x, k1.y);
        vv[u] = make_float4(v0.x, v0.y, v1.x, v1.y);
    }
    __syncthreads();
    if (t >= WN) return;
    float q[32];
    const __half2* qr = (const __half2*)(base + (size_t)t * 1152);
    #pragma unroll
    for (int j = 0; j < 16; j++) {
        float2 f = __half22float2(qr[j]);
        q[2*j] = f.x; q[2*j+1] = f.y;
    }
    float s[WN];
    #pragma unroll
    for (int m = 0; m < WN; m++) {
        float a = 0.0f;
        #pragma unroll
        for (int j = 0; j < 8; j++) {
            float4 f = kk[m*8 + j];
            a += q[4*j]*f.x + q[4*j+1]*f.y + q[4*j+2]*f.z + q[4*j+3]*f.w;
        }
        s[m] = a * 0.17677669529663687f;
    }
    float mx = -1e30f;
    #pragma unroll
    for (int m = 0; m < WN; m++) mx = fmaxf(mx, s[m]);
    float sum = 0.0f;
    #pragma unroll
    for (int m = 0; m < WN; m++) { s[m] = __expf(s[m] - mx); sum += s[m]; }
    float inv = 1.0f / sum;
    float o[32];
    #pragma unroll
    for (int j = 0; j < 32; j++) o[j] = 0.0f;
    #pragma unroll
    for (int m = 0; m < WN; m++) {
        float w = s[m] * inv;
        #pragma unroll
        for (int j = 0; j < 8; j++) {
            float4 f = vv[m*8 + j];
            o[4*j] += w*f.x; o[4*j+1] += w*f.y; o[4*j+2] += w*f.z; o[4*j+3] += w*f.w;
        }
    }
    int tok = win * WN + t;
    int k0 = head * 32;
    #pragma unroll
    for (int j = 0; j < 32; j += 2)
        h_store2(O, NTOK, tok, k0 + j, o[j], o[j + 1]);
}

// ---------------- fp16 GEMM: 128x128 CTA, stage = A16K + B16K, 3 stages ----------------
#define STAGES 3
#define STG_BYTES 32768
#define MBAR_OFF  98304
#define SMEM_DYN  (98304 + 64)

// EPI 0: qkv fp16   1: gelu -> chunked fp16   2: scatter+resid fp32   3: resid fp32
template<int EPI>
__global__ __launch_bounds__(256)
void gemm_mma(const __half* __restrict__ A, const __half* __restrict__ B,
              const float* __restrict__ bias, float* __restrict__ Co,
              __half* __restrict__ O2, const float* __restrict__ resid,
              int NC, int Nn)
{
    extern __shared__ __align__(1024) char sm[];
    uint32_t sb = smem_u32(sm);
    int tid = threadIdx.x, lane = tid & 31, wid = tid >> 5;
    int wm = wid & 1, wn = wid >> 1;           // 2(M) x 4(N) warps, warp tile 64x32
    int m0 = blockIdx.y * 128, n0 = blockIdx.x * 128;

    if (tid == 0) {
        #pragma unroll
        for (int s = 0; s < STAGES; s++) MBARRIER_INIT(sb + MBAR_OFF + s * 8, 1);
        FENCE_ASYNC();
    }
    __syncthreads();

    auto issue = [&](int j) {
        const char* asrc = (const char*)A + ((size_t)j * NTOK + m0) * 128;
        const char* bsrc = (const char*)B + ((size_t)j * Nn   + n0) * 128;
        int s = j % STAGES;
        uint32_t dst = sb + s * STG_BYTES;
        uint32_t mb  = sb + MBAR_OFF + s * 8;
        MBARRIER_EXPECT_TX(mb, 32768);
        BULK_G2S(dst,         asrc, 16384, mb);
        BULK_G2S(dst + 16384, bsrc, 16384, mb);
    };
    if (tid == 0) { issue(0); issue(1); issue(2); }

    float acc[4][4][4];
    #pragma unroll
    for (int i = 0; i < 4; i++)
        #pragma unroll
        for (int j = 0; j < 4; j++)
            #pragma unroll
            for (int u = 0; u < 4; u++) acc[i][j][u] = 0.0f;

    for (int i = 0; i < NC; i++) {
        int s = i % STAGES;
        MBARRIER_WAIT_PARITY(sb + MBAR_OFF + s * 8, (i / STAGES) & 1);

        uint32_t As = sb + s * STG_BYTES;
        uint32_t Bs = As + 16384;
        #pragma unroll
        for (int kk = 0; kk < 4; kk++) {
            int ch = kk * 2 + (lane >> 4);
            uint32_t b[4][2];
            #pragma unroll
            for (int j2 = 0; j2 < 2; j2++) {
                int row = wn * 32 + j2 * 16 + (lane & 15);
                uint32_t r0, r1, r2, r3;
                LDSM_X4(r0, r1, r2, r3,
                        Bs + (uint32_t)row * 128 + (uint32_t)((ch ^ (row & 7)) << 4));
                b[2*j2][0] = r0; b[2*j2][1] = r2;
                b[2*j2+1][0] = r1; b[2*j2+1][1] = r3;
            }
            #pragma unroll
            for (int ii = 0; ii < 4; ii++) {
                int row = wm * 64 + ii * 16 + (lane & 15);
                uint32_t a[4];
                LDSM_X4(a[0], a[1], a[2], a[3],
                        As + (uint32_t)row * 128 + (uint32_t)((ch ^ (row & 7)) << 4));
                #pragma unroll
                for (int j = 0; j < 4; j++) mma16816(acc[ii][j], a, b[j]);
            }
        }
        __syncthreads();
        if (tid == 0 && i + STAGES < NC) issue(i + STAGES);
    }

    // stage C through smem (fp32, stride 132) for coalesced epilogue
    float* smf = (float*)sm;
    #pragma unroll
    for (int i = 0; i < 4; i++)
        #pragma unroll
        for (int j = 0; j < 4; j++) {
            int br = wm * 64 + i * 16 + (lane >> 2);
            int bc = wn * 32 + j * 8 + 2 * (lane & 3);
            *(float2*)&smf[br * 132 + bc]       = make_float2(acc[i][j][0], acc[i][j][1]);
            *(float2*)&smf[(br + 8) * 132 + bc] = make_float2(acc[i][j][2], acc[i][j][3]);
        }
    __syncthreads();

    int r    = tid >> 1;
    int cb0  = (tid & 1) * 64;
    int grow = m0 + r;
    const float* srow = &smf[r * 132 + cb0];
    if (EPI == 0) {
        __half* dst = O2 + (size_t)grow * Nn + n0 + cb0;
        #pragma unroll
        for (int c = 0; c < 64; c += 2) {
            float v0 = srow[c]   + bias[n0+cb0+c];
            float v1 = srow[c+1] + bias[n0+cb0+c+1];
            *(__half2*)(dst + c) = __floats2half2_rn(v0, v1);
        }
    } else if (EPI == 1) {
        int gc0 = n0 + cb0;                    // multiple of 64
        int ch  = gc0 >> 6;
        __half* hp = O2 + ((size_t)ch * NTOK + grow) * 64;
        #pragma unroll
        for (int c = 0; c < 64; c += 2) {
            float v0 = srow[c]   + bias[gc0 + c];
            float v1 = srow[c+1] + bias[gc0 + c + 1];
            v0 = 0.5f * v0 * (1.0f + erff(v0 * 0.70710678118654752f));
            v1 = 0.5f * v1 * (1.0f + erff(v1 * 0.70710678118654752f));
            int idx = ((((c >> 3) & 7) ^ (grow & 7)) << 3) + (c & 7);
            *(__half2*)(hp + idx) = __floats2half2_rn(v0, v1);
        }
    } else {
        size_t orow = (EPI == 2) ? (size_t)win_to_seq(grow) * Nn : (size_t)grow * Nn;
        float* dst = Co + orow + n0 + cb0;
        const float* rp = resid + orow + n0 + cb0;
        #pragma unroll
        for (int c = 0; c < 64; c += 4) {
            float4 rr = *(const float4*)(rp + c);
            float4 o;
            o.x = srow[c+0] + bias[n0+cb0+c+0] + rr.x;
            o.y = srow[c+1] + bias[n0+cb0+c+1] + rr.y;
            o.z = srow[c+2] + bias[n0+cb0+c+2] + rr.z;
            o.w = srow[c+3] + bias[n0+cb0+c+3] + rr.w;
            *(float4*)(dst + c) = o;
        }
    }
}

// ---------------- launcher ----------------
extern "C" void kernel_launch(void* const* d_in, const int* in_sizes, int n_in,
                              void* d_out, int out_size)
{
    const float* x      = (const float*)d_in[0];
    const float* ln1_g  = (const float*)d_in[1];
    const float* ln1_b  = (const float*)d_in[2];
    const float* w_qkv  = (const float*)d_in[3];
    const float* b_qkv  = (const float*)d_in[4];
    const float* w_proj = (const float*)d_in[5];
    const float* b_proj = (const float*)d_in[6];
    const float* ln2_g  = (const float*)d_in[7];
    const float* ln2_b  = (const float*)d_in[8];
    const float* w_fc1  = (const float*)d_in[9];
    const float* b_fc1  = (const float*)d_in[10];
    const float* w_fc2  = (const float*)d_in[11];
    const float* b_fc2  = (const float*)d_in[12];
    float* out = (float*)d_out;

    __half *act, *hid, *qkv, *wq, *wp, *w1, *w2;
    float *xres;
    cudaGetSymbolAddress((void**)&act,  g_act);
    cudaGetSymbolAddress((void**)&hid,  g_hid);
    cudaGetSymbolAddress((void**)&qkv,  g_qkv);
    cudaGetSymbolAddress((void**)&xres, g_xres);
    cudaGetSymbolAddress((void**)&wq,   g_wq);
    cudaGetSymbolAddress((void**)&wp,   g_wp);
    cudaGetSymbolAddress((void**)&w1,   g_w1);
    cudaGetSymbolAddress((void**)&w2,   g_w2);

    cudaFuncSetAttribute(gemm_mma<0>, cudaFuncAttributeMaxDynamicSharedMemorySize, SMEM_DYN);
    cudaFuncSetAttribute(gemm_mma<1>, cudaFuncAttributeMaxDynamicSharedMemorySize, SMEM_DYN);
    cudaFuncSetAttribute(gemm_mma<2>, cudaFuncAttributeMaxDynamicSharedMemorySize, SMEM_DYN);
    cudaFuncSetAttribute(gemm_mma<3>, cudaFuncAttributeMaxDynamicSharedMemorySize, SMEM_DYN);

    // weight prep (single fp16)
    wprep<<<dim3(1152/32,  384/32), dim3(32, 8)>>>(w_qkv,  384,  1152, wq);
    wprep<<<dim3( 384/32,  384/32), dim3(32, 8)>>>(w_proj, 384,   384, wp);
    wprep<<<dim3(1536/32,  384/32), dim3(32, 8)>>>(w_fc1,  384,  1536, w1);
    wprep<<<dim3( 384/32, 1536/32), dim3(32, 8)>>>(w_fc2,  1536,  384, w2);

    const int MT = NTOK / 128;   // 784

    // 1) LN1 + roll + window partition -> act (window order)
    ln_kernel<true><<<NTOK / 8, 256>>>(x, ln1_g, ln1_b, act);
    // 2) QKV -> fp16
    gemm_mma<0><<<dim3(1152/128, MT), 256, SMEM_DYN>>>(act, wq, b_qkv, nullptr, qkv, nullptr, NC_A, 1152);
    // 3) attention -> act (window order)
    attn_kernel<<<dim3(NTOK / WN, 12), 64>>>(qkv, act);
    // 4) proj + reverse/roll + residual -> xres (sequence order)
    gemm_mma<2><<<dim3( 384/128, MT), 256, SMEM_DYN>>>(act, wp, b_proj, xres, nullptr, x, NC_A, 384);
    // 5) LN2 -> act (sequence order)
    ln_kernel<false><<<NTOK / 8, 256>>>(xres, ln2_g, ln2_b, act);
    // 6) FC1 + GELU -> hid (sequence order)
    gemm_mma<1><<<dim3(1536/128, MT), 256, SMEM_DYN>>>(act, w1, b_fc1, nullptr, hid, nullptr, NC_A, 1536);
    // 7) FC2 + residual -> out (sequence order)
    gemm_mma<3><<<dim3( 384/128, MT), 256, SMEM_DYN>>>(hid, w2, b_fc2, out, nullptr, xres, NC_H, 384);
}

// round 12
// speedup vs baseline: 1.0659x; 1.0152x over previous
#include <cuda_runtime.h>
#include <cuda_fp16.h>
#include <math.h>
#include <stdint.h>

// ---------------- problem constants ----------------
#define HHs   56
#define NTOK  100352
#define WN    49
#define NC_A  6      // K=384  -> 6 chunks of 64
#define NC_H  24     // K=1536 -> 24 chunks of 64

// ---------------- scratch: chunk-major, pre-swizzled fp16 layouts ----------------
__device__ __align__(1024) __half g_act[(size_t)NC_A * NTOK * 64];
__device__ __align__(1024) __half g_hid[(size_t)NC_H * NTOK * 64];
__device__ __align__(256) __half g_qkv [(size_t)NTOK * 1152];     // fp16 row-major
__device__ __align__(256) float  g_xres[(size_t)NTOK * 384];
// weights: [NC chunks][N][64] single fp16
__device__ __align__(1024) __half g_wq[(size_t)NC_A * 1152 * 64];
__device__ __align__(1024) __half g_wp[(size_t)NC_A *  384 * 64];
__device__ __align__(1024) __half g_w1[(size_t)NC_A * 1536 * 64];
__device__ __align__(1024) __half g_w2[(size_t)NC_H *  384 * 64];

// ---------------- PTX helpers ----------------
__device__ __forceinline__ uint32_t smem_u32(const void* p) {
    uint32_t a;
    asm("{ .reg .u64 t; cvta.to.shared.u64 t, %1; cvt.u32.u64 %0, t; }" : "=r"(a) : "l"(p));
    return a;
}
#define MBARRIER_INIT(mb, c) \
    asm volatile("mbarrier.init.shared.b64 [%0], %1;" :: "r"((uint32_t)(mb)), "r"((uint32_t)(c)) : "memory")
#define MBARRIER_EXPECT_TX(mb, n) \
    asm volatile("mbarrier.arrive.expect_tx.shared.b64 _, [%0], %1;" :: "r"((uint32_t)(mb)), "r"((uint32_t)(n)) : "memory")
#define MBARRIER_WAIT_PARITY(mb, par) do { \
    uint32_t _m = (uint32_t)(mb), _p = (uint32_t)(par), _d; \
    asm volatile("{\n\t.reg .pred p;\n\t" \
        "mbarrier.try_wait.parity.acquire.cta.shared::cta.b64 p, [%1], %2;\n\t" \
        "selp.b32 %0, 1, 0, p;\n\t}" : "=r"(_d) : "r"(_m), "r"(_p) : "memory"); \
    if (!_d) { \
        asm volatile("{\n\t.reg .pred P1;\n\t" \
            "WL_%=:\n\t" \
            "mbarrier.try_wait.parity.acquire.cta.shared::cta.b64 P1, [%0], %1, 0x989680;\n\t" \
            "@P1 bra.uni WD_%=;\n\t" \
            "bra.uni WL_%=;\n\t" \
            "WD_%=:\n\t}" :: "r"(_m), "r"(_p) : "memory"); \
    } } while (0)
#define BULK_G2S(dst, src, n, mb) \
    asm volatile("cp.async.bulk.shared::cluster.global.mbarrier::complete_tx::bytes [%0], [%1], %2, [%3];" \
        :: "r"((uint32_t)(dst)), "l"(src), "r"((uint32_t)(n)), "r"((uint32_t)(mb)) : "memory")
#define FENCE_ASYNC() asm volatile("fence.proxy.async.shared::cta;" ::: "memory")
#define LDSM_X4(r0, r1, r2, r3, addr) \
    asm volatile("ldmatrix.sync.aligned.m8n8.x4.shared.b16 {%0,%1,%2,%3}, [%4];" \
                 : "=r"(r0), "=r"(r1), "=r"(r2), "=r"(r3) : "r"(addr))

__device__ __forceinline__ void mma16816(float* c, const uint32_t* a, const uint32_t* b) {
    asm volatile("mma.sync.aligned.m16n8k16.row.col.f32.f16.f16.f32 "
        "{%0,%1,%2,%3}, {%4,%5,%6,%7}, {%8,%9}, {%0,%1,%2,%3};"
        : "+f"(c[0]), "+f"(c[1]), "+f"(c[2]), "+f"(c[3])
        : "r"(a[0]), "r"(a[1]), "r"(a[2]), "r"(a[3]), "r"(b[0]), "r"(b[1]));
}

// ---- packed fp32x2 helpers (sm_100+ PTX; full fp32 precision, half the issue count) ----
__device__ __forceinline__ unsigned long long pk2(float x, float y) {
    unsigned long long u;
    asm("mov.b64 %0, {%1, %2};" : "=l"(u) : "r"(__float_as_uint(x)), "r"(__float_as_uint(y)));
    return u;
}
__device__ __forceinline__ float2 upk2(unsigned long long u) {
    uint32_t x, y;
    asm("mov.b64 {%0, %1}, %2;" : "=r"(x), "=r"(y) : "l"(u));
    return make_float2(__uint_as_float(x), __uint_as_float(y));
}
#define FMA2(d, a, b, c) \
    asm("fma.rn.f32x2 %0, %1, %2, %3;" : "=l"(d) : "l"(a), "l"(b), "l"(c))

// window-order row -> sequence row (roll map; same both directions)
__device__ __forceinline__ int win_to_seq(int r) {
    int n  = r % WN;
    int t  = r / WN;
    int wc = t & 7, wr = (t >> 3) & 7, b = t >> 6;
    int n7 = n / 7;
    int h = wr * 7 + n7, w = wc * 7 + (n - n7 * 7);
    int dh = h + 3; if (dh >= HHs) dh -= HHs;
    int dw = w + 3; if (dw >= HHs) dw -= HHs;
    return (b * HHs + dh) * HHs + dw;
}

// fp16 store of 2 adjacent cols into chunk-major swizzled layout (k even)
__device__ __forceinline__ void h_store2(__half* base, int rows, int tok, int k,
                                         float v0, float v1) {
    int ch  = k >> 6;
    int idx = ((((k >> 3) & 7) ^ (tok & 7)) << 3) + (k & 7);
    *(__half2*)(base + ((size_t)ch * rows + tok) * 64 + idx) = __floats2half2_rn(v0, v1);
}

// ---------------- weight prep: W[K][N] fp32 -> [NC][N][64] swizzled fp16 ----------------
__global__ void wprep(const float* __restrict__ W, int K, int N, __half* __restrict__ O)
{
    __shared__ float t[32][33];
    int nb = blockIdx.x * 32, kb = blockIdx.y * 32;
    for (int i = threadIdx.y; i < 32; i += 8)
        t[i][threadIdx.x] = W[(size_t)(kb + i) * N + nb + threadIdx.x];
    __syncthreads();
    for (int i = threadIdx.y; i < 32; i += 8) {
        float v = t[threadIdx.x][i];
        int k = kb + threadIdx.x, n = nb + i;
        int ch  = k >> 6;
        int idx = ((((k >> 3) & 7) ^ (n & 7)) << 3) + (k & 7);
        O[((size_t)ch * N + n) * 64 + idx] = __float2half_rn(v);
    }
}

// ---------------- LayerNorm -> chunked fp16 (one warp per token) ----------------
template<bool PERM>
__global__ void ln_kernel(const float* __restrict__ X, const float* __restrict__ G,
                          const float* __restrict__ Bv, __half* __restrict__ Y)
{
    int gw   = (blockIdx.x * blockDim.x + threadIdx.x) >> 5;
    int lane = threadIdx.x & 31;
    if (gw >= NTOK) return;
    int src = PERM ? win_to_seq(gw) : gw;
    const float4* xr = (const float4*)(X + (size_t)src * 384);
    float4 a = xr[lane], b = xr[32 + lane], c = xr[64 + lane];
    float s = a.x+a.y+a.z+a.w + b.x+b.y+b.z+b.w + c.x+c.y+c.z+c.w;
    float q = a.x*a.x+a.y*a.y+a.z*a.z+a.w*a.w
            + b.x*b.x+b.y*b.y+b.z*b.z+b.w*b.w
            + c.x*c.x+c.y*c.y+c.z*c.z+c.w*c.w;
    #pragma unroll
    for (int o = 16; o; o >>= 1) {
        s += __shfl_xor_sync(0xffffffffu, s, o);
        q += __shfl_xor_sync(0xffffffffu, q, o);
    }
    float mu  = s * (1.0f / 384.0f);
    float var = q * (1.0f / 384.0f) - mu * mu;
    float rs  = rsqrtf(var + 1e-5f);
    const float4* gg = (const float4*)G;
    const float4* bb = (const float4*)Bv;
    #pragma unroll
    for (int seg = 0; seg < 3; seg++) {
        float4 v  = (seg == 0) ? a : (seg == 1) ? b : c;
        float4 g4 = gg[seg * 32 + lane];
        float4 b4 = bb[seg * 32 + lane];
        int k0 = seg * 128 + lane * 4;
        float w0 = (v.x - mu) * rs * g4.x + b4.x;
        float w1 = (v.y - mu) * rs * g4.y + b4.y;
        float w2 = (v.z - mu) * rs * g4.z + b4.z;
        float w3 = (v.w - mu) * rs * g4.w + b4.w;
        h_store2(Y, NTOK, gw, k0,     w0, w1);
        h_store2(Y, NTOK, gw, k0 + 2, w2, w3);
    }
}

// ---------------- attention: fp16 qkv in, packed f32x2 math ----------------
__global__ __launch_bounds__(64)
void attn_kernel(const __half* __restrict__ qkv, __half* __restrict__ O)
{
    __shared__ ulonglong2 kk[WN * 8], vv[WN * 8];   // packed f32x2 pairs (4 floats each)
    int win = blockIdx.x, head = blockIdx.y;
    int t = threadIdx.x;
    const __half* base = qkv + (size_t)win * WN * 1152 + head * 32;
    for (int u = t; u < WN * 8; u += 64) {
        int m = u >> 3, j = u & 7;
        const __half2* kp = (const __half2*)(base + (size_t)m * 1152 + 384 + j * 4);
        const __half2* vp = (const __half2*)(base + (size_t)m * 1152 + 768 + j * 4);
        float2 k0 = __half22float2(kp[0]), k1 = __half22float2(kp[1]);
        float2 v0 = __half22float2(vp[0]), v1 = __half22float2(vp[1]);
        ulonglong2 kq, vq;
        kq.x = pk2(k0.x, k0.y); kq.y = pk2(k1.x, k1.y);
        vq.x = pk2(v0.x, v0.y); vq.y = pk2(v1.x, v1.y);
        kk[u] = kq; vv[u] = vq;
    }
    __syncthreads();
    if (t >= WN) return;
    unsigned long long q2[16];
    const __half2* qr = (const __half2*)(base + (size_t)t * 1152);
    #pragma unroll
    for (int j = 0; j < 16; j++) {
        float2 f = __half22float2(qr[j]);
        q2[j] = pk2(f.x, f.y);
    }
    float s[WN];
    #pragma unroll
    for (int m = 0; m < WN; m++) {
        unsigned long long acc0 = pk2(0.0f, 0.0f), acc1 = pk2(0.0f, 0.0f);
        #pragma unroll
        for (int j = 0; j < 8; j++) {
            ulonglong2 kq = kk[m*8 + j];
            FMA2(acc0, q2[2*j],   kq.x, acc0);
            FMA2(acc1, q2[2*j+1], kq.y, acc1);
        }
        float2 a0 = upk2(acc0), a1 = upk2(acc1);
        s[m] = (a0.x + a0.y + a1.x + a1.y) * 0.17677669529663687f;
    }
    float mx = -1e30f;
    #pragma unroll
    for (int m = 0; m < WN; m++) mx = fmaxf(mx, s[m]);
    float sum = 0.0f;
    #pragma unroll
    for (int m = 0; m < WN; m++) { s[m] = __expf(s[m] - mx); sum += s[m]; }
    float inv = 1.0f / sum;
    unsigned long long o2[16];
    #pragma unroll
    for (int j = 0; j < 16; j++) o2[j] = pk2(0.0f, 0.0f);
    #pragma unroll
    for (int m = 0; m < WN; m++) {
        float w = s[m] * inv;
        unsigned long long w2 = pk2(w, w);
        #pragma unroll
        for (int j = 0; j < 8; j++) {
            ulonglong2 vq = vv[m*8 + j];
            FMA2(o2[2*j],   w2, vq.x, o2[2*j]);
            FMA2(o2[2*j+1], w2, vq.y, o2[2*j+1]);
        }
    }
    int tok = win * WN + t;
    int k0 = head * 32;
    #pragma unroll
    for (int j = 0; j < 16; j++) {
        float2 f = upk2(o2[j]);
        h_store2(O, NTOK, tok, k0 + 2*j, f.x, f.y);
    }
}

// ---------------- fp16 GEMM: 128x128 CTA, stage = A16K + B16K, 3 stages ----------------
#define STAGES 3
#define STG_BYTES 32768
#define MBAR_OFF  98304
#define SMEM_DYN  (98304 + 64)

// EPI 0: qkv fp16   1: gelu -> chunked fp16   2: scatter+resid fp32   3: resid fp32
template<int EPI>
__global__ __launch_bounds__(256)
void gemm_mma(const __half* __restrict__ A, const __half* __restrict__ B,
              const float* __restrict__ bias, float* __restrict__ Co,
              __half* __restrict__ O2, const float* __restrict__ resid,
              int NC, int Nn)
{
    extern __shared__ __align__(1024) char sm[];
    uint32_t sb = smem_u32(sm);
    int tid = threadIdx.x, lane = tid & 31, wid = tid >> 5;
    int wm = wid & 1, wn = wid >> 1;           // 2(M) x 4(N) warps, warp tile 64x32
    int m0 = blockIdx.y * 128, n0 = blockIdx.x * 128;

    if (tid == 0) {
        #pragma unroll
        for (int s = 0; s < STAGES; s++) MBARRIER_INIT(sb + MBAR_OFF + s * 8, 1);
        FENCE_ASYNC();
    }
    __syncthreads();

    auto issue = [&](int j) {
        const char* asrc = (const char*)A + ((size_t)j * NTOK + m0) * 128;
        const char* bsrc = (const char*)B + ((size_t)j * Nn   + n0) * 128;
        int s = j % STAGES;
        uint32_t dst = sb + s * STG_BYTES;
        uint32_t mb  = sb + MBAR_OFF + s * 8;
        MBARRIER_EXPECT_TX(mb, 32768);
        BULK_G2S(dst,         asrc, 16384, mb);
        BULK_G2S(dst + 16384, bsrc, 16384, mb);
    };
    if (tid == 0) { issue(0); issue(1); issue(2); }

    float acc[4][4][4];
    #pragma unroll
    for (int i = 0; i < 4; i++)
        #pragma unroll
        for (int j = 0; j < 4; j++)
            #pragma unroll
            for (int u = 0; u < 4; u++) acc[i][j][u] = 0.0f;

    for (int i = 0; i < NC; i++) {
        int s = i % STAGES;
        MBARRIER_WAIT_PARITY(sb + MBAR_OFF + s * 8, (i / STAGES) & 1);

        uint32_t As = sb + s * STG_BYTES;
        uint32_t Bs = As + 16384;
        #pragma unroll
        for (int kk = 0; kk < 4; kk++) {
            int ch = kk * 2 + (lane >> 4);
            uint32_t b[4][2];
            #pragma unroll
            for (int j2 = 0; j2 < 2; j2++) {
                int row = wn * 32 + j2 * 16 + (lane & 15);
                uint32_t r0, r1, r2, r3;
                LDSM_X4(r0, r1, r2, r3,
                        Bs + (uint32_t)row * 128 + (uint32_t)((ch ^ (row & 7)) << 4));
                b[2*j2][0] = r0; b[2*j2][1] = r2;
                b[2*j2+1][0] = r1; b[2*j2+1][1] = r3;
            }
            #pragma unroll
            for (int ii = 0; ii < 4; ii++) {
                int row = wm * 64 + ii * 16 + (lane & 15);
                uint32_t a[4];
                LDSM_X4(a[0], a[1], a[2], a[3],
                        As + (uint32_t)row * 128 + (uint32_t)((ch ^ (row & 7)) << 4));
                #pragma unroll
                for (int j = 0; j < 4; j++) mma16816(acc[ii][j], a, b[j]);
            }
        }
        __syncthreads();
        if (tid == 0 && i + STAGES < NC) issue(i + STAGES);
    }

    // stage C through smem (fp32, stride 132) for coalesced epilogue
    float* smf = (float*)sm;
    #pragma unroll
    for (int i = 0; i < 4; i++)
        #pragma unroll
        for (int j = 0; j < 4; j++) {
            int br = wm * 64 + i * 16 + (lane >> 2);
            int bc = wn * 32 + j * 8 + 2 * (lane & 3);
            *(float2*)&smf[br * 132 + bc]       = make_float2(acc[i][j][0], acc[i][j][1]);
            *(float2*)&smf[(br + 8) * 132 + bc] = make_float2(acc[i][j][2], acc[i][j][3]);
        }
    __syncthreads();

    int r    = tid >> 1;
    int cb0  = (tid & 1) * 64;
    int grow = m0 + r;
    const float* srow = &smf[r * 132 + cb0];
    if (EPI == 0) {
        __half* dst = O2 + (size_t)grow * Nn + n0 + cb0;
        #pragma unroll
        for (int c = 0; c < 64; c += 2) {
            float v0 = srow[c]   + bias[n0+cb0+c];
            float v1 = srow[c+1] + bias[n0+cb0+c+1];
            *(__half2*)(dst + c) = __floats2half2_rn(v0, v1);
        }
    } else if (EPI == 1) {
        int gc0 = n0 + cb0;                    // multiple of 64
        int ch  = gc0 >> 6;
        __half* hp = O2 + ((size_t)ch * NTOK + grow) * 64;
        #pragma unroll
        for (int c = 0; c < 64; c += 2) {
            float v0 = srow[c]   + bias[gc0 + c];
            float v1 = srow[c+1] + bias[gc0 + c + 1];
            v0 = 0.5f * v0 * (1.0f + erff(v0 * 0.70710678118654752f));
            v1 = 0.5f * v1 * (1.0f + erff(v1 * 0.70710678118654752f));
            int idx = ((((c >> 3) & 7) ^ (grow & 7)) << 3) + (c & 7);
            *(__half2*)(hp + idx) = __floats2half2_rn(v0, v1);
        }
    } else {
        size_t orow = (EPI == 2) ? (size_t)win_to_seq(grow) * Nn : (size_t)grow * Nn;
        float* dst = Co + orow + n0 + cb0;
        const float* rp = resid + orow + n0 + cb0;
        #pragma unroll
        for (int c = 0; c < 64; c += 4) {
            float4 rr = *(const float4*)(rp + c);
            float4 o;
            o.x = srow[c+0] + bias[n0+cb0+c+0] + rr.x;
            o.y = srow[c+1] + bias[n0+cb0+c+1] + rr.y;
            o.z = srow[c+2] + bias[n0+cb0+c+2] + rr.z;
            o.w = srow[c+3] + bias[n0+cb0+c+3] + rr.w;
            *(float4*)(dst + c) = o;
        }
    }
}

// ---------------- launcher ----------------
extern "C" void kernel_launch(void* const* d_in, const int* in_sizes, int n_in,
                              void* d_out, int out_size)
{
    const float* x      = (const float*)d_in[0];
    const float* ln1_g  = (const float*)d_in[1];
    const float* ln1_b  = (const float*)d_in[2];
    const float* w_qkv  = (const float*)d_in[3];
    const float* b_qkv  = (const float*)d_in[4];
    const float* w_proj = (const float*)d_in[5];
    const float* b_proj = (const float*)d_in[6];
    const float* ln2_g  = (const float*)d_in[7];
    const float* ln2_b  = (const float*)d_in[8];
    const float* w_fc1  = (const float*)d_in[9];
    const float* b_fc1  = (const float*)d_in[10];
    const float* w_fc2  = (const float*)d_in[11];
    const float* b_fc2  = (const float*)d_in[12];
    float* out = (float*)d_out;

    __half *act, *hid, *qkv, *wq, *wp, *w1, *w2;
    float *xres;
    cudaGetSymbolAddress((void**)&act,  g_act);
    cudaGetSymbolAddress((void**)&hid,  g_hid);
    cudaGetSymbolAddress((void**)&qkv,  g_qkv);
    cudaGetSymbolAddress((void**)&xres, g_xres);
    cudaGetSymbolAddress((void**)&wq,   g_wq);
    cudaGetSymbolAddress((void**)&wp,   g_wp);
    cudaGetSymbolAddress((void**)&w1,   g_w1);
    cudaGetSymbolAddress((void**)&w2,   g_w2);

    cudaFuncSetAttribute(gemm_mma<0>, cudaFuncAttributeMaxDynamicSharedMemorySize, SMEM_DYN);
    cudaFuncSetAttribute(gemm_mma<1>, cudaFuncAttributeMaxDynamicSharedMemorySize, SMEM_DYN);
    cudaFuncSetAttribute(gemm_mma<2>, cudaFuncAttributeMaxDynamicSharedMemorySize, SMEM_DYN);
    cudaFuncSetAttribute(gemm_mma<3>, cudaFuncAttributeMaxDynamicSharedMemorySize, SMEM_DYN);

    // weight prep (single fp16)
    wprep<<<dim3(1152/32,  384/32), dim3(32, 8)>>>(w_qkv,  384,  1152, wq);
    wprep<<<dim3( 384/32,  384/32), dim3(32, 8)>>>(w_proj, 384,   384, wp);
    wprep<<<dim3(1536/32,  384/32), dim3(32, 8)>>>(w_fc1,  384,  1536, w1);
    wprep<<<dim3( 384/32, 1536/32), dim3(32, 8)>>>(w_fc2,  1536,  384, w2);

    const int MT = NTOK / 128;   // 784

    // 1) LN1 + roll + window partition -> act (window order)
    ln_kernel<true><<<NTOK / 8, 256>>>(x, ln1_g, ln1_b, act);
    // 2) QKV -> fp16
    gemm_mma<0><<<dim3(1152/128, MT), 256, SMEM_DYN>>>(act, wq, b_qkv, nullptr, qkv, nullptr, NC_A, 1152);
    // 3) attention -> act (window order)
    attn_kernel<<<dim3(NTOK / WN, 12), 64>>>(qkv, act);
    // 4) proj + reverse/roll + residual -> xres (sequence order)
    gemm_mma<2><<<dim3( 384/128, MT), 256, SMEM_DYN>>>(act, wp, b_proj, xres, nullptr, x, NC_A, 384);
    // 5) LN2 -> act (sequence order)
    ln_kernel<false><<<NTOK / 8, 256>>>(xres, ln2_g, ln2_b, act);
    // 6) FC1 + GELU -> hid (sequence order)
    gemm_mma<1><<<dim3(1536/128, MT), 256, SMEM_DYN>>>(act, w1, b_fc1, nullptr, hid, nullptr, NC_A, 1536);
    // 7) FC2 + residual -> out (sequence order)
    gemm_mma<3><<<dim3( 384/128, MT), 256, SMEM_DYN>>>(hid, w2, b_fc2, out, nullptr, xres, NC_H, 384);
}

// round 13
// speedup vs baseline: 1.4240x; 1.3359x over previous
#include <cuda_runtime.h>
#include <cuda_fp16.h>
#include <math.h>
#include <stdint.h>

// ---------------- problem constants ----------------
#define HHs   56
#define NTOK  100352
#define WN    49
#define NC_A  6      // K=384  -> 6 chunks of 64
#define NC_H  24     // K=1536 -> 24 chunks of 64

// ---------------- scratch: chunk-major, pre-swizzled fp16 layouts ----------------
__device__ __align__(1024) __half g_act[(size_t)NC_A * NTOK * 64];
__device__ __align__(1024) __half g_hid[(size_t)NC_H * NTOK * 64];
__device__ __align__(256) __half g_qkv [(size_t)NTOK * 1152];     // fp16 row-major
__device__ __align__(256) float  g_xres[(size_t)NTOK * 384];
// weights: [NC chunks][N][64] single fp16
__device__ __align__(1024) __half g_wq[(size_t)NC_A * 1152 * 64];
__device__ __align__(1024) __half g_wp[(size_t)NC_A *  384 * 64];
__device__ __align__(1024) __half g_w1[(size_t)NC_A * 1536 * 64];
__device__ __align__(1024) __half g_w2[(size_t)NC_H *  384 * 64];

// ---------------- PTX helpers ----------------
__device__ __forceinline__ uint32_t smem_u32(const void* p) {
    uint32_t a;
    asm("{ .reg .u64 t; cvta.to.shared.u64 t, %1; cvt.u32.u64 %0, t; }" : "=r"(a) : "l"(p));
    return a;
}
#define MBARRIER_INIT(mb, c) \
    asm volatile("mbarrier.init.shared.b64 [%0], %1;" :: "r"((uint32_t)(mb)), "r"((uint32_t)(c)) : "memory")
#define MBARRIER_EXPECT_TX(mb, n) \
    asm volatile("mbarrier.arrive.expect_tx.shared.b64 _, [%0], %1;" :: "r"((uint32_t)(mb)), "r"((uint32_t)(n)) : "memory")
#define MBARRIER_ARRIVE(mb) \
    asm volatile("mbarrier.arrive.release.cta.shared.b64 _, [%0];" :: "r"((uint32_t)(mb)) : "memory")
#define MBARRIER_WAIT_PARITY(mb, par) do { \
    uint32_t _m = (uint32_t)(mb), _p = (uint32_t)(par), _d; \
    asm volatile("{\n\t.reg .pred p;\n\t" \
        "mbarrier.try_wait.parity.acquire.cta.shared::cta.b64 p, [%1], %2;\n\t" \
        "selp.b32 %0, 1, 0, p;\n\t}" : "=r"(_d) : "r"(_m), "r"(_p) : "memory"); \
    if (!_d) { \
        asm volatile("{\n\t.reg .pred P1;\n\t" \
            "WL_%=:\n\t" \
            "mbarrier.try_wait.parity.acquire.cta.shared::cta.b64 P1, [%0], %1, 0x989680;\n\t" \
            "@P1 bra.uni WD_%=;\n\t" \
            "bra.uni WL_%=;\n\t" \
            "WD_%=:\n\t}" :: "r"(_m), "r"(_p) : "memory"); \
    } } while (0)
#define BULK_G2S(dst, src, n, mb) \
    asm volatile("cp.async.bulk.shared::cluster.global.mbarrier::complete_tx::bytes [%0], [%1], %2, [%3];" \
        :: "r"((uint32_t)(dst)), "l"(src), "r"((uint32_t)(n)), "r"((uint32_t)(mb)) : "memory")
#define FENCE_ASYNC() asm volatile("fence.proxy.async.shared::cta;" ::: "memory")
#define LDSM_X4(r0, r1, r2, r3, addr) \
    asm volatile("ldmatrix.sync.aligned.m8n8.x4.shared.b16 {%0,%1,%2,%3}, [%4];" \
                 : "=r"(r0), "=r"(r1), "=r"(r2), "=r"(r3) : "r"(addr))

__device__ __forceinline__ void mma16816(float* c, const uint32_t* a, const uint32_t* b) {
    asm volatile("mma.sync.aligned.m16n8k16.row.col.f32.f16.f16.f32 "
        "{%0,%1,%2,%3}, {%4,%5,%6,%7}, {%8,%9}, {%0,%1,%2,%3};"
        : "+f"(c[0]), "+f"(c[1]), "+f"(c[2]), "+f"(c[3])
        : "r"(a[0]), "r"(a[1]), "r"(a[2]), "r"(a[3]), "r"(b[0]), "r"(b[1]));
}

// ---- packed fp32x2 helpers ----
__device__ __forceinline__ unsigned long long pk2(float x, float y) {
    unsigned long long u;
    asm("mov.b64 %0, {%1, %2};" : "=l"(u) : "r"(__float_as_uint(x)), "r"(__float_as_uint(y)));
    return u;
}
__device__ __forceinline__ float2 upk2(unsigned long long u) {
    uint32_t x, y;
    asm("mov.b64 {%0, %1}, %2;" : "=r"(x), "=r"(y) : "l"(u));
    return make_float2(__uint_as_float(x), __uint_as_float(y));
}
#define FMA2(d, a, b, c) \
    asm("fma.rn.f32x2 %0, %1, %2, %3;" : "=l"(d) : "l"(a), "l"(b), "l"(c))

// window-order row -> sequence row (roll map; same both directions)
__device__ __forceinline__ int win_to_seq(int r) {
    int n  = r % WN;
    int t  = r / WN;
    int wc = t & 7, wr = (t >> 3) & 7, b = t >> 6;
    int n7 = n / 7;
    int h = wr * 7 + n7, w = wc * 7 + (n - n7 * 7);
    int dh = h + 3; if (dh >= HHs) dh -= HHs;
    int dw = w + 3; if (dw >= HHs) dw -= HHs;
    return (b * HHs + dh) * HHs + dw;
}

// fp16 store of 2 adjacent cols into chunk-major swizzled layout (k even)
__device__ __forceinline__ void h_store2(__half* base, int rows, int tok, int k,
                                         float v0, float v1) {
    int ch  = k >> 6;
    int idx = ((((k >> 3) & 7) ^ (tok & 7)) << 3) + (k & 7);
    *(__half2*)(base + ((size_t)ch * rows + tok) * 64 + idx) = __floats2half2_rn(v0, v1);
}

// ---------------- weight prep: W[K][N] fp32 -> [NC][N][64] swizzled fp16 ----------------
__global__ void wprep(const float* __restrict__ W, int K, int N, __half* __restrict__ O)
{
    __shared__ float t[32][33];
    int nb = blockIdx.x * 32, kb = blockIdx.y * 32;
    for (int i = threadIdx.y; i < 32; i += 8)
        t[i][threadIdx.x] = W[(size_t)(kb + i) * N + nb + threadIdx.x];
    __syncthreads();
    for (int i = threadIdx.y; i < 32; i += 8) {
        float v = t[threadIdx.x][i];
        int k = kb + threadIdx.x, n = nb + i;
        int ch  = k >> 6;
        int idx = ((((k >> 3) & 7) ^ (n & 7)) << 3) + (k & 7);
        O[((size_t)ch * N + n) * 64 + idx] = __float2half_rn(v);
    }
}

// ---------------- LayerNorm -> chunked fp16 (one warp per token) ----------------
template<bool PERM>
__global__ void ln_kernel(const float* __restrict__ X, const float* __restrict__ G,
                          const float* __restrict__ Bv, __half* __restrict__ Y)
{
    int gw   = (blockIdx.x * blockDim.x + threadIdx.x) >> 5;
    int lane = threadIdx.x & 31;
    if (gw >= NTOK) return;
    int src = PERM ? win_to_seq(gw) : gw;
    const float4* xr = (const float4*)(X + (size_t)src * 384);
    float4 a = xr[lane], b = xr[32 + lane], c = xr[64 + lane];
    float s = a.x+a.y+a.z+a.w + b.x+b.y+b.z+b.w + c.x+c.y+c.z+c.w;
    float q = a.x*a.x+a.y*a.y+a.z*a.z+a.w*a.w
            + b.x*b.x+b.y*b.y+b.z*b.z+b.w*b.w
            + c.x*c.x+c.y*c.y+c.z*c.z+c.w*c.w;
    #pragma unroll
    for (int o = 16; o; o >>= 1) {
        s += __shfl_xor_sync(0xffffffffu, s, o);
        q += __shfl_xor_sync(0xffffffffu, q, o);
    }
    float mu  = s * (1.0f / 384.0f);
    float var = q * (1.0f / 384.0f) - mu * mu;
    float rs  = rsqrtf(var + 1e-5f);
    const float4* gg = (const float4*)G;
    const float4* bb = (const float4*)Bv;
    #pragma unroll
    for (int seg = 0; seg < 3; seg++) {
        float4 v  = (seg == 0) ? a : (seg == 1) ? b : c;
        float4 g4 = gg[seg * 32 + lane];
        float4 b4 = bb[seg * 32 + lane];
        int k0 = seg * 128 + lane * 4;
        float w0 = (v.x - mu) * rs * g4.x + b4.x;
        float w1 = (v.y - mu) * rs * g4.y + b4.y;
        float w2 = (v.z - mu) * rs * g4.z + b4.z;
        float w3 = (v.w - mu) * rs * g4.w + b4.w;
        h_store2(Y, NTOK, gw, k0,     w0, w1);
        h_store2(Y, NTOK, gw, k0 + 2, w2, w3);
    }
}

// ---------------- attention: fp16 qkv in, packed f32x2 math ----------------
__global__ __launch_bounds__(64)
void attn_kernel(const __half* __restrict__ qkv, __half* __restrict__ O)
{
    __shared__ ulonglong2 kk[WN * 8], vv[WN * 8];   // packed f32x2 pairs (4 floats each)
    int win = blockIdx.x, head = blockIdx.y;
    int t = threadIdx.x;
    const __half* base = qkv + (size_t)win * WN * 1152 + head * 32;
    for (int u = t; u < WN * 8; u += 64) {
        int m = u >> 3, j = u & 7;
        const __half2* kp = (const __half2*)(base + (size_t)m * 1152 + 384 + j * 4);
        const __half2* vp = (const __half2*)(base + (size_t)m * 1152 + 768 + j * 4);
        float2 k0 = __half22float2(kp[0]), k1 = __half22float2(kp[1]);
        float2 v0 = __half22float2(vp[0]), v1 = __half22float2(vp[1]);
        ulonglong2 kq, vq;
        kq.x = pk2(k0.x, k0.y); kq.y = pk2(k1.x, k1.y);
        vq.x = pk2(v0.x, v0.y); vq.y = pk2(v1.x, v1.y);
        kk[u] = kq; vv[u] = vq;
    }
    __syncthreads();
    if (t >= WN) return;
    unsigned long long q2[16];
    const __half2* qr = (const __half2*)(base + (size_t)t * 1152);
    #pragma unroll
    for (int j = 0; j < 16; j++) {
        float2 f = __half22float2(qr[j]);
        q2[j] = pk2(f.x, f.y);
    }
    float s[WN];
    #pragma unroll
    for (int m = 0; m < WN; m++) {
        unsigned long long acc0 = pk2(0.0f, 0.0f), acc1 = pk2(0.0f, 0.0f);
        #pragma unroll
        for (int j = 0; j < 8; j++) {
            ulonglong2 kq = kk[m*8 + j];
            FMA2(acc0, q2[2*j],   kq.x, acc0);
            FMA2(acc1, q2[2*j+1], kq.y, acc1);
        }
        float2 a0 = upk2(acc0), a1 = upk2(acc1);
        s[m] = (a0.x + a0.y + a1.x + a1.y) * 0.17677669529663687f;
    }
    float mx = -1e30f;
    #pragma unroll
    for (int m = 0; m < WN; m++) mx = fmaxf(mx, s[m]);
    float sum = 0.0f;
    #pragma unroll
    for (int m = 0; m < WN; m++) { s[m] = __expf(s[m] - mx); sum += s[m]; }
    float inv = 1.0f / sum;
    unsigned long long o2[16];
    #pragma unroll
    for (int j = 0; j < 16; j++) o2[j] = pk2(0.0f, 0.0f);
    #pragma unroll
    for (int m = 0; m < WN; m++) {
        float w = s[m] * inv;
        unsigned long long w2 = pk2(w, w);
        #pragma unroll
        for (int j = 0; j < 8; j++) {
            ulonglong2 vq = vv[m*8 + j];
            FMA2(o2[2*j],   w2, vq.x, o2[2*j]);
            FMA2(o2[2*j+1], w2, vq.y, o2[2*j+1]);
        }
    }
    int tok = win * WN + t;
    int k0 = head * 32;
    #pragma unroll
    for (int j = 0; j < 16; j++) {
        float2 f = upk2(o2[j]);
        h_store2(O, NTOK, tok, k0 + 2*j, f.x, f.y);
    }
}

// ---------------- fp16 GEMM: 128x128 CTA, 3 stages, empty-barrier pipeline ----------------
#define STAGES 3
#define STG_BYTES 32768
#define MBAR_OFF  98304          // full[0..2] at +0/+8/+16, empty[0..2] at +24/+32/+40
#define SMEM_DYN  (98304 + 64)

// EPI 0: qkv fp16   1: gelu -> chunked fp16   2: scatter+resid fp32   3: resid fp32
template<int EPI>
__global__ __launch_bounds__(256, 2)
void gemm_mma(const __half* __restrict__ A, const __half* __restrict__ B,
              const float* __restrict__ bias, float* __restrict__ Co,
              __half* __restrict__ O2, const float* __restrict__ resid,
              int NC, int Nn)
{
    extern __shared__ __align__(1024) char sm[];
    uint32_t sb = smem_u32(sm);
    int tid = threadIdx.x, lane = tid & 31, wid = tid >> 5;
    int wm = wid & 1, wn = wid >> 1;           // 2(M) x 4(N) warps, warp tile 64x32
    int m0 = blockIdx.y * 128, n0 = blockIdx.x * 128;

    if (tid == 0) {
        #pragma unroll
        for (int s = 0; s < STAGES; s++) {
            MBARRIER_INIT(sb + MBAR_OFF + s * 8, 1);        // full (tx)
            MBARRIER_INIT(sb + MBAR_OFF + 24 + s * 8, 8);   // empty (8 warps)
        }
        FENCE_ASYNC();
    }
    __syncthreads();

    auto issue = [&](int j) {
        const char* asrc = (const char*)A + ((size_t)j * NTOK + m0) * 128;
        const char* bsrc = (const char*)B + ((size_t)j * Nn   + n0) * 128;
        int s = j % STAGES;
        uint32_t dst = sb + s * STG_BYTES;
        uint32_t mb  = sb + MBAR_OFF + s * 8;
        MBARRIER_EXPECT_TX(mb, 32768);
        BULK_G2S(dst,         asrc, 16384, mb);
        BULK_G2S(dst + 16384, bsrc, 16384, mb);
    };
    if (tid == 0) { issue(0); issue(1); issue(2); }

    float acc[4][4][4];
    #pragma unroll
    for (int i = 0; i < 4; i++)
        #pragma unroll
        for (int j = 0; j < 4; j++)
            #pragma unroll
            for (int u = 0; u < 4; u++) acc[i][j][u] = 0.0f;

    for (int i = 0; i < NC; i++) {
        int s = i % STAGES;
        MBARRIER_WAIT_PARITY(sb + MBAR_OFF + s * 8, (i / STAGES) & 1);

        uint32_t As = sb + s * STG_BYTES;
        uint32_t Bs = As + 16384;
        #pragma unroll
        for (int kk = 0; kk < 4; kk++) {
            int ch = kk * 2 + (lane >> 4);
            uint32_t b[4][2];
            #pragma unroll
            for (int j2 = 0; j2 < 2; j2++) {
                int row = wn * 32 + j2 * 16 + (lane & 15);
                uint32_t r0, r1, r2, r3;
                LDSM_X4(r0, r1, r2, r3,
                        Bs + (uint32_t)row * 128 + (uint32_t)((ch ^ (row & 7)) << 4));
                b[2*j2][0] = r0; b[2*j2][1] = r2;
                b[2*j2+1][0] = r1; b[2*j2+1][1] = r3;
            }
            #pragma unroll
            for (int ii = 0; ii < 4; ii++) {
                int row = wm * 64 + ii * 16 + (lane & 15);
                uint32_t a[4];
                LDSM_X4(a[0], a[1], a[2], a[3],
                        As + (uint32_t)row * 128 + (uint32_t)((ch ^ (row & 7)) << 4));
                #pragma unroll
                for (int j = 0; j < 4; j++) mma16816(acc[ii][j], a, b[j]);
            }
        }
        // this warp is done reading stage s -> arrive empty
        __syncwarp();
        if (lane == 0) MBARRIER_ARRIVE(sb + MBAR_OFF + 24 + s * 8);
        // producer refills slot s once all 8 warps arrived
        if (tid == 0 && i + STAGES < NC) {
            MBARRIER_WAIT_PARITY(sb + MBAR_OFF + 24 + s * 8, (i / STAGES) & 1);
            issue(i + STAGES);
        }
    }

    // ---- direct register epilogue (no smem staging, no syncs) ----
    // thread fragment: rows r0 = m0+wm*64+ii*16+(lane>>2), r0+8; cols c0 = n0+wn*32+j*8+2*(lane&3)
    int cbase = n0 + wn * 32 + 2 * (lane & 3);
    float2 bv[4];
    #pragma unroll
    for (int j = 0; j < 4; j++) bv[j] = *(const float2*)(bias + cbase + j * 8);
    #pragma unroll
    for (int ii = 0; ii < 4; ii++) {
        #pragma unroll
        for (int half = 0; half < 2; half++) {
            int grow = m0 + wm * 64 + ii * 16 + (lane >> 2) + half * 8;
            size_t orow;
            const float* rp = nullptr;
            if (EPI == 2) { orow = (size_t)win_to_seq(grow) * Nn; rp = resid + orow; }
            else if (EPI == 3) { orow = (size_t)grow * Nn; rp = resid + orow; }
            else orow = (size_t)grow * Nn;
            #pragma unroll
            for (int j = 0; j < 4; j++) {
                int gcol = cbase + j * 8;
                float v0 = acc[ii][j][2*half]   + bv[j].x;
                float v1 = acc[ii][j][2*half+1] + bv[j].y;
                if (EPI == 0) {
                    *(__half2*)(O2 + (size_t)grow * Nn + gcol) = __floats2half2_rn(v0, v1);
                } else if (EPI == 1) {
                    v0 = 0.5f * v0 * (1.0f + erff(v0 * 0.70710678118654752f));
                    v1 = 0.5f * v1 * (1.0f + erff(v1 * 0.70710678118654752f));
                    h_store2(O2, NTOK, grow, gcol, v0, v1);
                } else {
                    float2 rr = *(const float2*)(rp + gcol);
                    *(float2*)(Co + orow + gcol) = make_float2(v0 + rr.x, v1 + rr.y);
                }
            }
        }
    }
}

// ---------------- launcher ----------------
extern "C" void kernel_launch(void* const* d_in, const int* in_sizes, int n_in,
                              void* d_out, int out_size)
{
    const float* x      = (const float*)d_in[0];
    const float* ln1_g  = (const float*)d_in[1];
    const float* ln1_b  = (const float*)d_in[2];
    const float* w_qkv  = (const float*)d_in[3];
    const float* b_qkv  = (const float*)d_in[4];
    const float* w_proj = (const float*)d_in[5];
    const float* b_proj = (const float*)d_in[6];
    const float* ln2_g  = (const float*)d_in[7];
    const float* ln2_b  = (const float*)d_in[8];
    const float* w_fc1  = (const float*)d_in[9];
    const float* b_fc1  = (const float*)d_in[10];
    const float* w_fc2  = (const float*)d_in[11];
    const float* b_fc2  = (const float*)d_in[12];
    float* out = (float*)d_out;

    __half *act, *hid, *qkv, *wq, *wp, *w1, *w2;
    float *xres;
    cudaGetSymbolAddress((void**)&act,  g_act);
    cudaGetSymbolAddress((void**)&hid,  g_hid);
    cudaGetSymbolAddress((void**)&qkv,  g_qkv);
    cudaGetSymbolAddress((void**)&xres, g_xres);
    cudaGetSymbolAddress((void**)&wq,   g_wq);
    cudaGetSymbolAddress((void**)&wp,   g_wp);
    cudaGetSymbolAddress((void**)&w1,   g_w1);
    cudaGetSymbolAddress((void**)&w2,   g_w2);

    cudaFuncSetAttribute(gemm_mma<0>, cudaFuncAttributeMaxDynamicSharedMemorySize, SMEM_DYN);
    cudaFuncSetAttribute(gemm_mma<1>, cudaFuncAttributeMaxDynamicSharedMemorySize, SMEM_DYN);
    cudaFuncSetAttribute(gemm_mma<2>, cudaFuncAttributeMaxDynamicSharedMemorySize, SMEM_DYN);
    cudaFuncSetAttribute(gemm_mma<3>, cudaFuncAttributeMaxDynamicSharedMemorySize, SMEM_DYN);

    // weight prep (single fp16)
    wprep<<<dim3(1152/32,  384/32), dim3(32, 8)>>>(w_qkv,  384,  1152, wq);
    wprep<<<dim3( 384/32,  384/32), dim3(32, 8)>>>(w_proj, 384,   384, wp);
    wprep<<<dim3(1536/32,  384/32), dim3(32, 8)>>>(w_fc1,  384,  1536, w1);
    wprep<<<dim3( 384/32, 1536/32), dim3(32, 8)>>>(w_fc2,  1536,  384, w2);

    const int MT = NTOK / 128;   // 784

    // 1) LN1 + roll + window partition -> act (window order)
    ln_kernel<true><<<NTOK / 8, 256>>>(x, ln1_g, ln1_b, act);
    // 2) QKV -> fp16
    gemm_mma<0><<<dim3(1152/128, MT), 256, SMEM_DYN>>>(act, wq, b_qkv, nullptr, qkv, nullptr, NC_A, 1152);
    // 3) attention -> act (window order)
    attn_kernel<<<dim3(NTOK / WN, 12), 64>>>(qkv, act);
    // 4) proj + reverse/roll + residual -> xres (sequence order)
    gemm_mma<2><<<dim3( 384/128, MT), 256, SMEM_DYN>>>(act, wp, b_proj, xres, nullptr, x, NC_A, 384);
    // 5) LN2 -> act (sequence order)
    ln_kernel<false><<<NTOK / 8, 256>>>(xres, ln2_g, ln2_b, act);
    // 6) FC1 + GELU -> hid (sequence order)
    gemm_mma<1><<<dim3(1536/128, MT), 256, SMEM_DYN>>>(act, w1, b_fc1, nullptr, hid, nullptr, NC_A, 1536);
    // 7) FC2 + residual -> out (sequence order)
    gemm_mma<3><<<dim3( 384/128, MT), 256, SMEM_DYN>>>(hid, w2, b_fc2, out, nullptr, xres, NC_H, 384);
}

// round 15
// speedup vs baseline: 1.4566x; 1.0229x over previous
#include <cuda_runtime.h>
#include <cuda_fp16.h>
#include <math.h>
#include <stdint.h>

// ---------------- problem constants ----------------
#define HHs   56
#define NTOK  100352
#define WN    49
#define NC_A  6      // K=384  -> 6 chunks of 64
#define NC_H  24     // K=1536 -> 24 chunks of 64

// ---------------- scratch: chunk-major, pre-swizzled fp16 layouts ----------------
__device__ __align__(1024) __half g_act[(size_t)NC_A * NTOK * 64];
__device__ __align__(1024) __half g_hid[(size_t)NC_H * NTOK * 64];
__device__ __align__(256) __half g_qkv [(size_t)NTOK * 1152];     // fp16 row-major
__device__ __align__(256) float  g_xres[(size_t)NTOK * 384];
// weights: [NC chunks][N][64] single fp16
__device__ __align__(1024) __half g_wq[(size_t)NC_A * 1152 * 64];
__device__ __align__(1024) __half g_wp[(size_t)NC_A *  384 * 64];
__device__ __align__(1024) __half g_w1[(size_t)NC_A * 1536 * 64];
__device__ __align__(1024) __half g_w2[(size_t)NC_H *  384 * 64];

// ---------------- PTX helpers ----------------
__device__ __forceinline__ uint32_t smem_u32(const void* p) {
    uint32_t a;
    asm("{ .reg .u64 t; cvta.to.shared.u64 t, %1; cvt.u32.u64 %0, t; }" : "=r"(a) : "l"(p));
    return a;
}
#define MBARRIER_INIT(mb, c) \
    asm volatile("mbarrier.init.shared.b64 [%0], %1;" :: "r"((uint32_t)(mb)), "r"((uint32_t)(c)) : "memory")
#define MBARRIER_EXPECT_TX(mb, n) \
    asm volatile("mbarrier.arrive.expect_tx.shared.b64 _, [%0], %1;" :: "r"((uint32_t)(mb)), "r"((uint32_t)(n)) : "memory")
#define MBARRIER_ARRIVE(mb) \
    asm volatile("mbarrier.arrive.release.cta.shared.b64 _, [%0];" :: "r"((uint32_t)(mb)) : "memory")
#define MBARRIER_WAIT_PARITY(mb, par) do { \
    uint32_t _m = (uint32_t)(mb), _p = (uint32_t)(par), _d; \
    asm volatile("{\n\t.reg .pred p;\n\t" \
        "mbarrier.try_wait.parity.acquire.cta.shared::cta.b64 p, [%1], %2;\n\t" \
        "selp.b32 %0, 1, 0, p;\n\t}" : "=r"(_d) : "r"(_m), "r"(_p) : "memory"); \
    if (!_d) { \
        asm volatile("{\n\t.reg .pred P1;\n\t" \
            "WL_%=:\n\t" \
            "mbarrier.try_wait.parity.acquire.cta.shared::cta.b64 P1, [%0], %1, 0x989680;\n\t" \
            "@P1 bra.uni WD_%=;\n\t" \
            "bra.uni WL_%=;\n\t" \
            "WD_%=:\n\t}" :: "r"(_m), "r"(_p) : "memory"); \
    } } while (0)
#define BULK_G2S(dst, src, n, mb) \
    asm volatile("cp.async.bulk.shared::cluster.global.mbarrier::complete_tx::bytes [%0], [%1], %2, [%3];" \
        :: "r"((uint32_t)(dst)), "l"(src), "r"((uint32_t)(n)), "r"((uint32_t)(mb)) : "memory")
#define FENCE_ASYNC() asm volatile("fence.proxy.async.shared::cta;" ::: "memory")
#define LDSM_X4(r0, r1, r2, r3, addr) \
    asm volatile("ldmatrix.sync.aligned.m8n8.x4.shared.b16 {%0,%1,%2,%3}, [%4];" \
                 : "=r"(r0), "=r"(r1), "=r"(r2), "=r"(r3) : "r"(addr))

__device__ __forceinline__ void mma16816(float* c, const uint32_t* a, const uint32_t* b) {
    asm volatile("mma.sync.aligned.m16n8k16.row.col.f32.f16.f16.f32 "
        "{%0,%1,%2,%3}, {%4,%5,%6,%7}, {%8,%9}, {%0,%1,%2,%3};"
        : "+f"(c[0]), "+f"(c[1]), "+f"(c[2]), "+f"(c[3])
        : "r"(a[0]), "r"(a[1]), "r"(a[2]), "r"(a[3]), "r"(b[0]), "r"(b[1]));
}

// ---- packed fp32x2 helpers ----
__device__ __forceinline__ unsigned long long pk2(float x, float y) {
    unsigned long long u;
    asm("mov.b64 %0, {%1, %2};" : "=l"(u) : "r"(__float_as_uint(x)), "r"(__float_as_uint(y)));
    return u;
}
__device__ __forceinline__ float2 upk2(unsigned long long u) {
    uint32_t x, y;
    asm("mov.b64 {%0, %1}, %2;" : "=r"(x), "=r"(y) : "l"(u));
    return make_float2(__uint_as_float(x), __uint_as_float(y));
}
#define FMA2(d, a, b, c) \
    asm("fma.rn.f32x2 %0, %1, %2, %3;" : "=l"(d) : "l"(a), "l"(b), "l"(c))

// window-order row -> sequence row (roll map; same both directions)
__device__ __forceinline__ int win_to_seq(int r) {
    int n  = r % WN;
    int t  = r / WN;
    int wc = t & 7, wr = (t >> 3) & 7, b = t >> 6;
    int n7 = n / 7;
    int h = wr * 7 + n7, w = wc * 7 + (n - n7 * 7);
    int dh = h + 3; if (dh >= HHs) dh -= HHs;
    int dw = w + 3; if (dw >= HHs) dw -= HHs;
    return (b * HHs + dh) * HHs + dw;
}

// fp16 store of 2 adjacent cols into chunk-major swizzled layout (k even)
__device__ __forceinline__ void h_store2(__half* base, int rows, int tok, int k,
                                         float v0, float v1) {
    int ch  = k >> 6;
    int idx = ((((k >> 3) & 7) ^ (tok & 7)) << 3) + (k & 7);
    *(__half2*)(base + ((size_t)ch * rows + tok) * 64 + idx) = __floats2half2_rn(v0, v1);
}

// ---------------- weight prep: W[K][N] fp32 -> [NC][N][64] swizzled fp16 ----------------
__global__ void wprep(const float* __restrict__ W, int K, int N, __half* __restrict__ O)
{
    __shared__ float t[32][33];
    int nb = blockIdx.x * 32, kb = blockIdx.y * 32;
    for (int i = threadIdx.y; i < 32; i += 8)
        t[i][threadIdx.x] = W[(size_t)(kb + i) * N + nb + threadIdx.x];
    __syncthreads();
    for (int i = threadIdx.y; i < 32; i += 8) {
        float v = t[threadIdx.x][i];
        int k = kb + threadIdx.x, n = nb + i;
        int ch  = k >> 6;
        int idx = ((((k >> 3) & 7) ^ (n & 7)) << 3) + (k & 7);
        O[((size_t)ch * N + n) * 64 + idx] = __float2half_rn(v);
    }
}

// ---------------- LayerNorm -> chunked fp16 (one warp per token) ----------------
template<bool PERM>
__global__ void ln_kernel(const float* __restrict__ X, const float* __restrict__ G,
                          const float* __restrict__ Bv, __half* __restrict__ Y)
{
    int gw   = (blockIdx.x * blockDim.x + threadIdx.x) >> 5;
    int lane = threadIdx.x & 31;
    if (gw >= NTOK) return;
    int src = PERM ? win_to_seq(gw) : gw;
    const float4* xr = (const float4*)(X + (size_t)src * 384);
    float4 a = xr[lane], b = xr[32 + lane], c = xr[64 + lane];
    float s = a.x+a.y+a.z+a.w + b.x+b.y+b.z+b.w + c.x+c.y+c.z+c.w;
    float q = a.x*a.x+a.y*a.y+a.z*a.z+a.w*a.w
            + b.x*b.x+b.y*b.y+b.z*b.z+b.w*b.w
            + c.x*c.x+c.y*c.y+c.z*c.z+c.w*c.w;
    #pragma unroll
    for (int o = 16; o; o >>= 1) {
        s += __shfl_xor_sync(0xffffffffu, s, o);
        q += __shfl_xor_sync(0xffffffffu, q, o);
    }
    float mu  = s * (1.0f / 384.0f);
    float var = q * (1.0f / 384.0f) - mu * mu;
    float rs  = rsqrtf(var + 1e-5f);
    const float4* gg = (const float4*)G;
    const float4* bb = (const float4*)Bv;
    #pragma unroll
    for (int seg = 0; seg < 3; seg++) {
        float4 v  = (seg == 0) ? a : (seg == 1) ? b : c;
        float4 g4 = gg[seg * 32 + lane];
        float4 b4 = bb[seg * 32 + lane];
        int k0 = seg * 128 + lane * 4;
        float w0 = (v.x - mu) * rs * g4.x + b4.x;
        float w1 = (v.y - mu) * rs * g4.y + b4.y;
        float w2 = (v.z - mu) * rs * g4.z + b4.z;
        float w3 = (v.w - mu) * rs * g4.w + b4.w;
        h_store2(Y, NTOK, gw, k0,     w0, w1);
        h_store2(Y, NTOK, gw, k0 + 2, w2, w3);
    }
}

// ---------------- attention: fp16 qkv in, packed f32x2 math ----------------
__global__ __launch_bounds__(64)
void attn_kernel(const __half* __restrict__ qkv, __half* __restrict__ O)
{
    __shared__ ulonglong2 kk[WN * 8], vv[WN * 8];   // packed f32x2 pairs (4 floats each)
    int win = blockIdx.x, head = blockIdx.y;
    int t = threadIdx.x;
    const __half* base = qkv + (size_t)win * WN * 1152 + head * 32;
    for (int u = t; u < WN * 8; u += 64) {
        int m = u >> 3, j = u & 7;
        const __half2* kp = (const __half2*)(base + (size_t)m * 1152 + 384 + j * 4);
        const __half2* vp = (const __half2*)(base + (size_t)m * 1152 + 768 + j * 4);
        float2 k0 = __half22float2(kp[0]), k1 = __half22float2(kp[1]);
        float2 v0 = __half22float2(vp[0]), v1 = __half22float2(vp[1]);
        ulonglong2 kq, vq;
        kq.x = pk2(k0.x, k0.y); kq.y = pk2(k1.x, k1.y);
        vq.x = pk2(v0.x, v0.y); vq.y = pk2(v1.x, v1.y);
        kk[u] = kq; vv[u] = vq;
    }
    __syncthreads();
    if (t >= WN) return;
    unsigned long long q2[16];
    const __half2* qr = (const __half2*)(base + (size_t)t * 1152);
    #pragma unroll
    for (int j = 0; j < 16; j++) {
        float2 f = __half22float2(qr[j]);
        q2[j] = pk2(f.x, f.y);
    }
    float s[WN];
    #pragma unroll
    for (int m = 0; m < WN; m++) {
        unsigned long long acc0 = pk2(0.0f, 0.0f), acc1 = pk2(0.0f, 0.0f);
        #pragma unroll
        for (int j = 0; j < 8; j++) {
            ulonglong2 kq = kk[m*8 + j];
            FMA2(acc0, q2[2*j],   kq.x, acc0);
            FMA2(acc1, q2[2*j+1], kq.y, acc1);
        }
        float2 a0 = upk2(acc0), a1 = upk2(acc1);
        s[m] = (a0.x + a0.y + a1.x + a1.y) * 0.17677669529663687f;
    }
    float mx = -1e30f;
    #pragma unroll
    for (int m = 0; m < WN; m++) mx = fmaxf(mx, s[m]);
    float sum = 0.0f;
    #pragma unroll
    for (int m = 0; m < WN; m++) { s[m] = __expf(s[m] - mx); sum += s[m]; }
    float inv = 1.0f / sum;
    unsigned long long o2[16];
    #pragma unroll
    for (int j = 0; j < 16; j++) o2[j] = pk2(0.0f, 0.0f);
    #pragma unroll
    for (int m = 0; m < WN; m++) {
        float w = s[m] * inv;
        unsigned long long w2 = pk2(w, w);
        #pragma unroll
        for (int j = 0; j < 8; j++) {
            ulonglong2 vq = vv[m*8 + j];
            FMA2(o2[2*j],   w2, vq.x, o2[2*j]);
            FMA2(o2[2*j+1], w2, vq.y, o2[2*j+1]);
        }
    }
    int tok = win * WN + t;
    int k0 = head * 32;
    #pragma unroll
    for (int j = 0; j < 16; j++) {
        float2 f = upk2(o2[j]);
        h_store2(O, NTOK, tok, k0 + 2*j, f.x, f.y);
    }
}

// ---------------- fp16 GEMM: 128x128 CTA, 3 stages, rotating producer + proxy fence ----------------
#define STAGES 3
#define STG_BYTES 32768
#define MBAR_OFF  98304          // full[0..2] at +0/+8/+16, empty[0..2] at +24/+32/+40
#define SMEM_DYN  (98304 + 64)

// EPI 0: qkv fp16   1: gelu -> chunked fp16   2: scatter+resid fp32   3: resid fp32
template<int EPI>
__global__ __launch_bounds__(256, 2)
void gemm_mma(const __half* __restrict__ A, const __half* __restrict__ B,
              const float* __restrict__ bias, float* __restrict__ Co,
              __half* __restrict__ O2, const float* __restrict__ resid,
              int NC, int Nn)
{
    extern __shared__ __align__(1024) char sm[];
    uint32_t sb = smem_u32(sm);
    int tid = threadIdx.x, lane = tid & 31, wid = tid >> 5;
    int wm = wid & 1, wn = wid >> 1;           // 2(M) x 4(N) warps, warp tile 64x32
    int m0 = blockIdx.y * 128, n0 = blockIdx.x * 128;

    if (tid == 0) {
        #pragma unroll
        for (int s = 0; s < STAGES; s++) {
            MBARRIER_INIT(sb + MBAR_OFF + s * 8, 1);        // full (tx)
            MBARRIER_INIT(sb + MBAR_OFF + 24 + s * 8, 8);   // empty (8 warps)
        }
        FENCE_ASYNC();
    }
    __syncthreads();

    auto issue = [&](int j) {
        const char* asrc = (const char*)A + ((size_t)j * NTOK + m0) * 128;
        const char* bsrc = (const char*)B + ((size_t)j * Nn   + n0) * 128;
        int s = j % STAGES;
        uint32_t dst = sb + s * STG_BYTES;
        uint32_t mb  = sb + MBAR_OFF + s * 8;
        MBARRIER_EXPECT_TX(mb, 32768);
        BULK_G2S(dst,         asrc, 16384, mb);
        BULK_G2S(dst + 16384, bsrc, 16384, mb);
    };
    if (tid == 0) { issue(0); issue(1); issue(2); }

    float acc[4][4][4];
    #pragma unroll
    for (int i = 0; i < 4; i++)
        #pragma unroll
        for (int j = 0; j < 4; j++)
            #pragma unroll
            for (int u = 0; u < 4; u++) acc[i][j][u] = 0.0f;

    for (int i = 0; i < NC; i++) {
        int s = i % STAGES;
        MBARRIER_WAIT_PARITY(sb + MBAR_OFF + s * 8, (i / STAGES) & 1);

        uint32_t As = sb + s * STG_BYTES;
        uint32_t Bs = As + 16384;
        #pragma unroll
        for (int kk = 0; kk < 4; kk++) {
            int ch = kk * 2 + (lane >> 4);
            uint32_t b[4][2];
            #pragma unroll
            for (int j2 = 0; j2 < 2; j2++) {
                int row = wn * 32 + j2 * 16 + (lane & 15);
                uint32_t r0, r1, r2, r3;
                LDSM_X4(r0, r1, r2, r3,
                        Bs + (uint32_t)row * 128 + (uint32_t)((ch ^ (row & 7)) << 4));
                b[2*j2][0] = r0; b[2*j2][1] = r2;
                b[2*j2+1][0] = r1; b[2*j2+1][1] = r3;
            }
            #pragma unroll
            for (int ii = 0; ii < 4; ii++) {
                int row = wm * 64 + ii * 16 + (lane & 15);
                uint32_t a[4];
                LDSM_X4(a[0], a[1], a[2], a[3],
                        As + (uint32_t)row * 128 + (uint32_t)((ch ^ (row & 7)) << 4));
                #pragma unroll
                for (int j = 0; j < 4; j++) mma16816(acc[ii][j], a, b[j]);
            }
        }
        // this warp is done reading stage s -> arrive empty (release orders its ldsm reads)
        __syncwarp();
        if (lane == 0) MBARRIER_ARRIVE(sb + MBAR_OFF + 24 + s * 8);
        // rotating producer: warp (i % 8) refills slot s once all warps arrived.
        // fence.proxy.async after the acquire orders the consumers' generic-proxy
        // reads against the async-proxy bulk write (cross-proxy hazard).
        if (i + STAGES < NC && wid == (i & 7)) {
            if (lane == 0) {
                MBARRIER_WAIT_PARITY(sb + MBAR_OFF + 24 + s * 8, (i / STAGES) & 1);
                FENCE_ASYNC();
                issue(i + STAGES);
            }
            __syncwarp();
        }
    }

    // ---- direct register epilogue (no smem staging, no syncs) ----
    int cbase = n0 + wn * 32 + 2 * (lane & 3);
    float2 bv[4];
    #pragma unroll
    for (int j = 0; j < 4; j++) bv[j] = *(const float2*)(bias + cbase + j * 8);
    #pragma unroll
    for (int ii = 0; ii < 4; ii++) {
        #pragma unroll
        for (int half = 0; half < 2; half++) {
            int grow = m0 + wm * 64 + ii * 16 + (lane >> 2) + half * 8;
            size_t orow;
            const float* rp = nullptr;
            if (EPI == 2) { orow = (size_t)win_to_seq(grow) * Nn; rp = resid + orow; }
            else if (EPI == 3) { orow = (size_t)grow * Nn; rp = resid + orow; }
            else orow = (size_t)grow * Nn;
            #pragma unroll
            for (int j = 0; j < 4; j++) {
                int gcol = cbase + j * 8;
                float v0 = acc[ii][j][2*half]   + bv[j].x;
                float v1 = acc[ii][j][2*half+1] + bv[j].y;
                if (EPI == 0) {
                    *(__half2*)(O2 + (size_t)grow * Nn + gcol) = __floats2half2_rn(v0, v1);
                } else if (EPI == 1) {
                    v0 = 0.5f * v0 * (1.0f + erff(v0 * 0.70710678118654752f));
                    v1 = 0.5f * v1 * (1.0f + erff(v1 * 0.70710678118654752f));
                    h_store2(O2, NTOK, grow, gcol, v0, v1);
                } else {
                    float2 rr = *(const float2*)(rp + gcol);
                    *(float2*)(Co + orow + gcol) = make_float2(v0 + rr.x, v1 + rr.y);
                }
            }
        }
    }
}

// ---------------- launcher ----------------
extern "C" void kernel_launch(void* const* d_in, const int* in_sizes, int n_in,
                              void* d_out, int out_size)
{
    const float* x      = (const float*)d_in[0];
    const float* ln1_g  = (const float*)d_in[1];
    const float* ln1_b  = (const float*)d_in[2];
    const float* w_qkv  = (const float*)d_in[3];
    const float* b_qkv  = (const float*)d_in[4];
    const float* w_proj = (const float*)d_in[5];
    const float* b_proj = (const float*)d_in[6];
    const float* ln2_g  = (const float*)d_in[7];
    const float* ln2_b  = (const float*)d_in[8];
    const float* w_fc1  = (const float*)d_in[9];
    const float* b_fc1  = (const float*)d_in[10];
    const float* w_fc2  = (const float*)d_in[11];
    const float* b_fc2  = (const float*)d_in[12];
    float* out = (float*)d_out;

    __half *act, *hid, *qkv, *wq, *wp, *w1, *w2;
    float *xres;
    cudaGetSymbolAddress((void**)&act,  g_act);
    cudaGetSymbolAddress((void**)&hid,  g_hid);
    cudaGetSymbolAddress((void**)&qkv,  g_qkv);
    cudaGetSymbolAddress((void**)&xres, g_xres);
    cudaGetSymbolAddress((void**)&wq,   g_wq);
    cudaGetSymbolAddress((void**)&wp,   g_wp);
    cudaGetSymbolAddress((void**)&w1,   g_w1);
    cudaGetSymbolAddress((void**)&w2,   g_w2);

    cudaFuncSetAttribute(gemm_mma<0>, cudaFuncAttributeMaxDynamicSharedMemorySize, SMEM_DYN);
    cudaFuncSetAttribute(gemm_mma<1>, cudaFuncAttributeMaxDynamicSharedMemorySize, SMEM_DYN);
    cudaFuncSetAttribute(gemm_mma<2>, cudaFuncAttributeMaxDynamicSharedMemorySize, SMEM_DYN);
    cudaFuncSetAttribute(gemm_mma<3>, cudaFuncAttributeMaxDynamicSharedMemorySize, SMEM_DYN);

    // weight prep (single fp16)
    wprep<<<dim3(1152/32,  384/32), dim3(32, 8)>>>(w_qkv,  384,  1152, wq);
    wprep<<<dim3( 384/32,  384/32), dim3(32, 8)>>>(w_proj, 384,   384, wp);
    wprep<<<dim3(1536/32,  384/32), dim3(32, 8)>>>(w_fc1,  384,  1536, w1);
    wprep<<<dim3( 384/32, 1536/32), dim3(32, 8)>>>(w_fc2,  1536,  384, w2);

    const int MT = NTOK / 128;   // 784

    // 1) LN1 + roll + window partition -> act (window order)
    ln_kernel<true><<<NTOK / 8, 256>>>(x, ln1_g, ln1_b, act);
    // 2) QKV -> fp16
    gemm_mma<0><<<dim3(1152/128, MT), 256, SMEM_DYN>>>(act, wq, b_qkv, nullptr, qkv, nullptr, NC_A, 1152);
    // 3) attention -> act (window order)
    attn_kernel<<<dim3(NTOK / WN, 12), 64>>>(qkv, act);
    // 4) proj + reverse/roll + residual -> xres (sequence order)
    gemm_mma<2><<<dim3( 384/128, MT), 256, SMEM_DYN>>>(act, wp, b_proj, xres, nullptr, x, NC_A, 384);
    // 5) LN2 -> act (sequence order)
    ln_kernel<false><<<NTOK / 8, 256>>>(xres, ln2_g, ln2_b, act);
    // 6) FC1 + GELU -> hid (sequence order)
    gemm_mma<1><<<dim3(1536/128, MT), 256, SMEM_DYN>>>(act, w1, b_fc1, nullptr, hid, nullptr, NC_A, 1536);
    // 7) FC2 + residual -> out (sequence order)
    gemm_mma<3><<<dim3( 384/128, MT), 256, SMEM_DYN>>>(hid, w2, b_fc2, out, nullptr, xres, NC_H, 384);
}

// round 16
// speedup vs baseline: 1.5545x; 1.0672x over previous
#include <cuda_runtime.h>
#include <cuda_fp16.h>
#include <math.h>
#include <stdint.h>

// ---------------- problem constants ----------------
#define HHs   56
#define NTOK  100352
#define WN    49
#define NC_A  6      // K=384  -> 6 chunks of 64
#define NC_H  24     // K=1536 -> 24 chunks of 64

// ---------------- scratch: chunk-major, pre-swizzled fp16 layouts ----------------
__device__ __align__(1024) __half g_act[(size_t)NC_A * NTOK * 64];
__device__ __align__(1024) __half g_hid[(size_t)NC_H * NTOK * 64];
__device__ __align__(256) __half g_qkv [(size_t)NTOK * 1152];     // fp16 row-major
__device__ __align__(256) float  g_xres[(size_t)NTOK * 384];
// weights: [NC chunks][N][64] single fp16
__device__ __align__(1024) __half g_wq[(size_t)NC_A * 1152 * 64];
__device__ __align__(1024) __half g_wp[(size_t)NC_A *  384 * 64];
__device__ __align__(1024) __half g_w1[(size_t)NC_A * 1536 * 64];
__device__ __align__(1024) __half g_w2[(size_t)NC_H *  384 * 64];

// ---------------- PTX helpers ----------------
__device__ __forceinline__ uint32_t smem_u32(const void* p) {
    uint32_t a;
    asm("{ .reg .u64 t; cvta.to.shared.u64 t, %1; cvt.u32.u64 %0, t; }" : "=r"(a) : "l"(p));
    return a;
}
#define MBARRIER_INIT(mb, c) \
    asm volatile("mbarrier.init.shared.b64 [%0], %1;" :: "r"((uint32_t)(mb)), "r"((uint32_t)(c)) : "memory")
#define MBARRIER_EXPECT_TX(mb, n) \
    asm volatile("mbarrier.arrive.expect_tx.shared.b64 _, [%0], %1;" :: "r"((uint32_t)(mb)), "r"((uint32_t)(n)) : "memory")
#define MBARRIER_ARRIVE(mb) \
    asm volatile("mbarrier.arrive.release.cta.shared.b64 _, [%0];" :: "r"((uint32_t)(mb)) : "memory")
#define MBARRIER_WAIT_PARITY(mb, par) do { \
    uint32_t _m = (uint32_t)(mb), _p = (uint32_t)(par), _d; \
    asm volatile("{\n\t.reg .pred p;\n\t" \
        "mbarrier.try_wait.parity.acquire.cta.shared::cta.b64 p, [%1], %2;\n\t" \
        "selp.b32 %0, 1, 0, p;\n\t}" : "=r"(_d) : "r"(_m), "r"(_p) : "memory"); \
    if (!_d) { \
        asm volatile("{\n\t.reg .pred P1;\n\t" \
            "WL_%=:\n\t" \
            "mbarrier.try_wait.parity.acquire.cta.shared::cta.b64 P1, [%0], %1, 0x989680;\n\t" \
            "@P1 bra.uni WD_%=;\n\t" \
            "bra.uni WL_%=;\n\t" \
            "WD_%=:\n\t}" :: "r"(_m), "r"(_p) : "memory"); \
    } } while (0)
#define BULK_G2S(dst, src, n, mb) \
    asm volatile("cp.async.bulk.shared::cluster.global.mbarrier::complete_tx::bytes [%0], [%1], %2, [%3];" \
        :: "r"((uint32_t)(dst)), "l"(src), "r"((uint32_t)(n)), "r"((uint32_t)(mb)) : "memory")
#define FENCE_ASYNC() asm volatile("fence.proxy.async.shared::cta;" ::: "memory")
#define LDSM_X4(r0, r1, r2, r3, addr) \
    asm volatile("ldmatrix.sync.aligned.m8n8.x4.shared.b16 {%0,%1,%2,%3}, [%4];" \
                 : "=r"(r0), "=r"(r1), "=r"(r2), "=r"(r3) : "r"(addr))

__device__ __forceinline__ void mma16816(float* c, const uint32_t* a, const uint32_t* b) {
    asm volatile("mma.sync.aligned.m16n8k16.row.col.f32.f16.f16.f32 "
        "{%0,%1,%2,%3}, {%4,%5,%6,%7}, {%8,%9}, {%0,%1,%2,%3};"
        : "+f"(c[0]), "+f"(c[1]), "+f"(c[2]), "+f"(c[3])
        : "r"(a[0]), "r"(a[1]), "r"(a[2]), "r"(a[3]), "r"(b[0]), "r"(b[1]));
}

// ---- packed fp32x2 helpers ----
__device__ __forceinline__ unsigned long long pk2(float x, float y) {
    unsigned long long u;
    asm("mov.b64 %0, {%1, %2};" : "=l"(u) : "r"(__float_as_uint(x)), "r"(__float_as_uint(y)));
    return u;
}
__device__ __forceinline__ float2 upk2(unsigned long long u) {
    uint32_t x, y;
    asm("mov.b64 {%0, %1}, %2;" : "=r"(x), "=r"(y) : "l"(u));
    return make_float2(__uint_as_float(x), __uint_as_float(y));
}
#define FMA2(d, a, b, c) \
    asm("fma.rn.f32x2 %0, %1, %2, %3;" : "=l"(d) : "l"(a), "l"(b), "l"(c))

// fast GELU (tanh form, HW tanh.approx)
__device__ __forceinline__ float gelu_fast(float v) {
    float u = 0.7978845608028654f * (v + 0.044715f * v * v * v);
    float th;
    asm("tanh.approx.f32 %0, %1;" : "=f"(th) : "f"(u));
    return 0.5f * v * (1.0f + th);
}

// window-order row -> sequence row (roll map; same both directions)
__device__ __forceinline__ int win_to_seq(int r) {
    int n  = r % WN;
    int t  = r / WN;
    int wc = t & 7, wr = (t >> 3) & 7, b = t >> 6;
    int n7 = n / 7;
    int h = wr * 7 + n7, w = wc * 7 + (n - n7 * 7);
    int dh = h + 3; if (dh >= HHs) dh -= HHs;
    int dw = w + 3; if (dw >= HHs) dw -= HHs;
    return (b * HHs + dh) * HHs + dw;
}

// fp16 store of 2 adjacent cols into chunk-major swizzled layout (k even)
__device__ __forceinline__ void h_store2(__half* base, int rows, int tok, int k,
                                         float v0, float v1) {
    int ch  = k >> 6;
    int idx = ((((k >> 3) & 7) ^ (tok & 7)) << 3) + (k & 7);
    *(__half2*)(base + ((size_t)ch * rows + tok) * 64 + idx) = __floats2half2_rn(v0, v1);
}

// ---------------- merged weight prep: all 4 weights in one launch ----------------
// segment boundaries (32x32 tiles): wq 36x12=432, wp 12x12=144, w1 48x12=576, w2 12x48=576
__global__ void wprep_all(const float* __restrict__ Wq, const float* __restrict__ Wp,
                          const float* __restrict__ W1, const float* __restrict__ W2,
                          __half* __restrict__ Oq, __half* __restrict__ Op,
                          __half* __restrict__ O1, __half* __restrict__ O2)
{
    __shared__ float t[32][33];
    int b = blockIdx.x;
    const float* W; __half* O; int K, N, nx;
    if (b < 432)       { W = Wq; O = Oq; K = 384;  N = 1152; nx = 36; }
    else if (b < 576)  { b -= 432;  W = Wp; O = Op; K = 384;  N = 384;  nx = 12; }
    else if (b < 1152) { b -= 576;  W = W1; O = O1; K = 384;  N = 1536; nx = 48; }
    else               { b -= 1152; W = W2; O = O2; K = 1536; N = 384;  nx = 12; }
    int nb = (b % nx) * 32, kb = (b / nx) * 32;
    for (int i = threadIdx.y; i < 32; i += 8)
        t[i][threadIdx.x] = W[(size_t)(kb + i) * N + nb + threadIdx.x];
    __syncthreads();
    for (int i = threadIdx.y; i < 32; i += 8) {
        float v = t[threadIdx.x][i];
        int k = kb + threadIdx.x, n = nb + i;
        int ch  = k >> 6;
        int idx = ((((k >> 3) & 7) ^ (n & 7)) << 3) + (k & 7);
        O[((size_t)ch * N + n) * 64 + idx] = __float2half_rn(v);
    }
}

// ---------------- LayerNorm -> chunked fp16 (one warp per token) ----------------
template<bool PERM>
__global__ void ln_kernel(const float* __restrict__ X, const float* __restrict__ G,
                          const float* __restrict__ Bv, __half* __restrict__ Y)
{
    int gw   = (blockIdx.x * blockDim.x + threadIdx.x) >> 5;
    int lane = threadIdx.x & 31;
    if (gw >= NTOK) return;
    int src = PERM ? win_to_seq(gw) : gw;
    const float4* xr = (const float4*)(X + (size_t)src * 384);
    float4 a = xr[lane], b = xr[32 + lane], c = xr[64 + lane];
    float s = a.x+a.y+a.z+a.w + b.x+b.y+b.z+b.w + c.x+c.y+c.z+c.w;
    float q = a.x*a.x+a.y*a.y+a.z*a.z+a.w*a.w
            + b.x*b.x+b.y*b.y+b.z*b.z+b.w*b.w
            + c.x*c.x+c.y*c.y+c.z*c.z+c.w*c.w;
    #pragma unroll
    for (int o = 16; o; o >>= 1) {
        s += __shfl_xor_sync(0xffffffffu, s, o);
        q += __shfl_xor_sync(0xffffffffu, q, o);
    }
    float mu  = s * (1.0f / 384.0f);
    float var = q * (1.0f / 384.0f) - mu * mu;
    float rs  = rsqrtf(var + 1e-5f);
    const float4* gg = (const float4*)G;
    const float4* bb = (const float4*)Bv;
    #pragma unroll
    for (int seg = 0; seg < 3; seg++) {
        float4 v  = (seg == 0) ? a : (seg == 1) ? b : c;
        float4 g4 = gg[seg * 32 + lane];
        float4 b4 = bb[seg * 32 + lane];
        int k0 = seg * 128 + lane * 4;
        float w0 = (v.x - mu) * rs * g4.x + b4.x;
        float w1 = (v.y - mu) * rs * g4.y + b4.y;
        float w2 = (v.z - mu) * rs * g4.z + b4.z;
        float w3 = (v.w - mu) * rs * g4.w + b4.w;
        h_store2(Y, NTOK, gw, k0,     w0, w1);
        h_store2(Y, NTOK, gw, k0 + 2, w2, w3);
    }
}

// ---------------- attention: fp16 qkv in, packed f32x2 math ----------------
__global__ __launch_bounds__(64)
void attn_kernel(const __half* __restrict__ qkv, __half* __restrict__ O)
{
    __shared__ ulonglong2 kk[WN * 8], vv[WN * 8];   // packed f32x2 pairs (4 floats each)
    int win = blockIdx.x, head = blockIdx.y;
    int t = threadIdx.x;
    const __half* base = qkv + (size_t)win * WN * 1152 + head * 32;
    for (int u = t; u < WN * 8; u += 64) {
        int m = u >> 3, j = u & 7;
        const __half2* kp = (const __half2*)(base + (size_t)m * 1152 + 384 + j * 4);
        const __half2* vp = (const __half2*)(base + (size_t)m * 1152 + 768 + j * 4);
        float2 k0 = __half22float2(kp[0]), k1 = __half22float2(kp[1]);
        float2 v0 = __half22float2(vp[0]), v1 = __half22float2(vp[1]);
        ulonglong2 kq, vq;
        kq.x = pk2(k0.x, k0.y); kq.y = pk2(k1.x, k1.y);
        vq.x = pk2(v0.x, v0.y); vq.y = pk2(v1.x, v1.y);
        kk[u] = kq; vv[u] = vq;
    }
    __syncthreads();
    if (t >= WN) return;
    unsigned long long q2[16];
    const __half2* qr = (const __half2*)(base + (size_t)t * 1152);
    #pragma unroll
    for (int j = 0; j < 16; j++) {
        float2 f = __half22float2(qr[j]);
        q2[j] = pk2(f.x, f.y);
    }
    float s[WN];
    #pragma unroll
    for (int m = 0; m < WN; m++) {
        unsigned long long acc0 = pk2(0.0f, 0.0f), acc1 = pk2(0.0f, 0.0f);
        #pragma unroll
        for (int j = 0; j < 8; j++) {
            ulonglong2 kq = kk[m*8 + j];
            FMA2(acc0, q2[2*j],   kq.x, acc0);
            FMA2(acc1, q2[2*j+1], kq.y, acc1);
        }
        float2 a0 = upk2(acc0), a1 = upk2(acc1);
        s[m] = (a0.x + a0.y + a1.x + a1.y) * 0.17677669529663687f;
    }
    float mx = -1e30f;
    #pragma unroll
    for (int m = 0; m < WN; m++) mx = fmaxf(mx, s[m]);
    float sum = 0.0f;
    #pragma unroll
    for (int m = 0; m < WN; m++) { s[m] = __expf(s[m] - mx); sum += s[m]; }
    float inv = 1.0f / sum;
    unsigned long long o2[16];
    #pragma unroll
    for (int j = 0; j < 16; j++) o2[j] = pk2(0.0f, 0.0f);
    #pragma unroll
    for (int m = 0; m < WN; m++) {
        float w = s[m] * inv;
        unsigned long long w2 = pk2(w, w);
        #pragma unroll
        for (int j = 0; j < 8; j++) {
            ulonglong2 vq = vv[m*8 + j];
            FMA2(o2[2*j],   w2, vq.x, o2[2*j]);
            FMA2(o2[2*j+1], w2, vq.y, o2[2*j+1]);
        }
    }
    int tok = win * WN + t;
    int k0 = head * 32;
    #pragma unroll
    for (int j = 0; j < 16; j++) {
        float2 f = upk2(o2[j]);
        h_store2(O, NTOK, tok, k0 + 2*j, f.x, f.y);
    }
}

// ---------------- fp16 GEMM: 128x128 CTA, 3 stages, rotating producer + proxy fence ----------------
#define STAGES 3
#define STG_BYTES 32768
#define MBAR_OFF  98304          // full[0..2] at +0/+8/+16, empty[0..2] at +24/+32/+40
#define SMEM_DYN  (98304 + 64)

// EPI 0: qkv fp16   1: gelu -> chunked fp16   2: scatter+resid fp32   3: resid fp32
template<int EPI>
__global__ __launch_bounds__(256, 2)
void gemm_mma(const __half* __restrict__ A, const __half* __restrict__ B,
              const float* __restrict__ bias, float* __restrict__ Co,
              __half* __restrict__ O2, const float* __restrict__ resid,
              int NC, int Nn)
{
    extern __shared__ __align__(1024) char sm[];
    uint32_t sb = smem_u32(sm);
    int tid = threadIdx.x, lane = tid & 31, wid = tid >> 5;
    int wm = wid & 1, wn = wid >> 1;           // 2(M) x 4(N) warps, warp tile 64x32
    int m0 = blockIdx.y * 128, n0 = blockIdx.x * 128;

    if (tid == 0) {
        #pragma unroll
        for (int s = 0; s < STAGES; s++) {
            MBARRIER_INIT(sb + MBAR_OFF + s * 8, 1);        // full (tx)
            MBARRIER_INIT(sb + MBAR_OFF + 24 + s * 8, 8);   // empty (8 warps)
        }
        FENCE_ASYNC();
    }
    __syncthreads();

    auto issue = [&](int j) {
        const char* asrc = (const char*)A + ((size_t)j * NTOK + m0) * 128;
        const char* bsrc = (const char*)B + ((size_t)j * Nn   + n0) * 128;
        int s = j % STAGES;
        uint32_t dst = sb + s * STG_BYTES;
        uint32_t mb  = sb + MBAR_OFF + s * 8;
        MBARRIER_EXPECT_TX(mb, 32768);
        BULK_G2S(dst,         asrc, 16384, mb);
        BULK_G2S(dst + 16384, bsrc, 16384, mb);
    };
    if (tid == 0) { issue(0); issue(1); issue(2); }

    float acc[4][4][4];
    #pragma unroll
    for (int i = 0; i < 4; i++)
        #pragma unroll
        for (int j = 0; j < 4; j++)
            #pragma unroll
            for (int u = 0; u < 4; u++) acc[i][j][u] = 0.0f;

    for (int i = 0; i < NC; i++) {
        int s = i % STAGES;
        MBARRIER_WAIT_PARITY(sb + MBAR_OFF + s * 8, (i / STAGES) & 1);

        uint32_t As = sb + s * STG_BYTES;
        uint32_t Bs = As + 16384;
        #pragma unroll
        for (int kk = 0; kk < 4; kk++) {
            int ch = kk * 2 + (lane >> 4);
            uint32_t b[4][2];
            #pragma unroll
            for (int j2 = 0; j2 < 2; j2++) {
                int row = wn * 32 + j2 * 16 + (lane & 15);
                uint32_t r0, r1, r2, r3;
                LDSM_X4(r0, r1, r2, r3,
                        Bs + (uint32_t)row * 128 + (uint32_t)((ch ^ (row & 7)) << 4));
                b[2*j2][0] = r0; b[2*j2][1] = r2;
                b[2*j2+1][0] = r1; b[2*j2+1][1] = r3;
            }
            #pragma unroll
            for (int ii = 0; ii < 4; ii++) {
                int row = wm * 64 + ii * 16 + (lane & 15);
                uint32_t a[4];
                LDSM_X4(a[0], a[1], a[2], a[3],
                        As + (uint32_t)row * 128 + (uint32_t)((ch ^ (row & 7)) << 4));
                #pragma unroll
                for (int j = 0; j < 4; j++) mma16816(acc[ii][j], a, b[j]);
            }
        }
        // this warp is done reading stage s -> arrive empty (release orders its ldsm reads)
        __syncwarp();
        if (lane == 0) MBARRIER_ARRIVE(sb + MBAR_OFF + 24 + s * 8);
        // rotating producer: warp (i % 8) refills slot s once all warps arrived.
        // fence.proxy.async orders consumers' generic-proxy reads vs async-proxy bulk write.
        if (i + STAGES < NC && wid == (i & 7)) {
            if (lane == 0) {
                MBARRIER_WAIT_PARITY(sb + MBAR_OFF + 24 + s * 8, (i / STAGES) & 1);
                FENCE_ASYNC();
                issue(i + STAGES);
            }
            __syncwarp();
        }
    }

    // ---- direct register epilogue (no smem staging, no syncs) ----
    int cbase = n0 + wn * 32 + 2 * (lane & 3);
    float2 bv[4];
    #pragma unroll
    for (int j = 0; j < 4; j++) bv[j] = *(const float2*)(bias + cbase + j * 8);
    #pragma unroll
    for (int ii = 0; ii < 4; ii++) {
        #pragma unroll
        for (int half = 0; half < 2; half++) {
            int grow = m0 + wm * 64 + ii * 16 + (lane >> 2) + half * 8;
            size_t orow;
            const float* rp = nullptr;
            if (EPI == 2) { orow = (size_t)win_to_seq(grow) * Nn; rp = resid + orow; }
            else if (EPI == 3) { orow = (size_t)grow * Nn; rp = resid + orow; }
            else orow = (size_t)grow * Nn;
            #pragma unroll
            for (int j = 0; j < 4; j++) {
                int gcol = cbase + j * 8;
                float v0 = acc[ii][j][2*half]   + bv[j].x;
                float v1 = acc[ii][j][2*half+1] + bv[j].y;
                if (EPI == 0) {
                    *(__half2*)(O2 + (size_t)grow * Nn + gcol) = __floats2half2_rn(v0, v1);
                } else if (EPI == 1) {
                    v0 = gelu_fast(v0);
                    v1 = gelu_fast(v1);
                    h_store2(O2, NTOK, grow, gcol, v0, v1);
                } else {
                    float2 rr = *(const float2*)(rp + gcol);
                    *(float2*)(Co + orow + gcol) = make_float2(v0 + rr.x, v1 + rr.y);
                }
            }
        }
    }
}

// ---------------- launcher ----------------
extern "C" void kernel_launch(void* const* d_in, const int* in_sizes, int n_in,
                              void* d_out, int out_size)
{
    const float* x      = (const float*)d_in[0];
    const float* ln1_g  = (const float*)d_in[1];
    const float* ln1_b  = (const float*)d_in[2];
    const float* w_qkv  = (const float*)d_in[3];
    const float* b_qkv  = (const float*)d_in[4];
    const float* w_proj = (const float*)d_in[5];
    const float* b_proj = (const float*)d_in[6];
    const float* ln2_g  = (const float*)d_in[7];
    const float* ln2_b  = (const float*)d_in[8];
    const float* w_fc1  = (const float*)d_in[9];
    const float* b_fc1  = (const float*)d_in[10];
    const float* w_fc2  = (const float*)d_in[11];
    const float* b_fc2  = (const float*)d_in[12];
    float* out = (float*)d_out;

    __half *act, *hid, *qkv, *wq, *wp, *w1, *w2;
    float *xres;
    cudaGetSymbolAddress((void**)&act,  g_act);
    cudaGetSymbolAddress((void**)&hid,  g_hid);
    cudaGetSymbolAddress((void**)&qkv,  g_qkv);
    cudaGetSymbolAddress((void**)&xres, g_xres);
    cudaGetSymbolAddress((void**)&wq,   g_wq);
    cudaGetSymbolAddress((void**)&wp,   g_wp);
    cudaGetSymbolAddress((void**)&w1,   g_w1);
    cudaGetSymbolAddress((void**)&w2,   g_w2);

    cudaFuncSetAttribute(gemm_mma<0>, cudaFuncAttributeMaxDynamicSharedMemorySize, SMEM_DYN);
    cudaFuncSetAttribute(gemm_mma<1>, cudaFuncAttributeMaxDynamicSharedMemorySize, SMEM_DYN);
    cudaFuncSetAttribute(gemm_mma<2>, cudaFuncAttributeMaxDynamicSharedMemorySize, SMEM_DYN);
    cudaFuncSetAttribute(gemm_mma<3>, cudaFuncAttributeMaxDynamicSharedMemorySize, SMEM_DYN);

    // weight prep (single merged launch)
    wprep_all<<<1728, dim3(32, 8)>>>(w_qkv, w_proj, w_fc1, w_fc2, wq, wp, w1, w2);

    const int MT = NTOK / 128;   // 784

    // 1) LN1 + roll + window partition -> act (window order)
    ln_kernel<true><<<NTOK / 8, 256>>>(x, ln1_g, ln1_b, act);
    // 2) QKV -> fp16
    gemm_mma<0><<<dim3(1152/128, MT), 256, SMEM_DYN>>>(act, wq, b_qkv, nullptr, qkv, nullptr, NC_A, 1152);
    // 3) attention -> act (window order)
    attn_kernel<<<dim3(NTOK / WN, 12), 64>>>(qkv, act);
    // 4) proj + reverse/roll + residual -> xres (sequence order)
    gemm_mma<2><<<dim3( 384/128, MT), 256, SMEM_DYN>>>(act, wp, b_proj, xres, nullptr, x, NC_A, 384);
    // 5) LN2 -> act (sequence order)
    ln_kernel<false><<<NTOK / 8, 256>>>(xres, ln2_g, ln2_b, act);
    // 6) FC1 + fast GELU -> hid (sequence order)
    gemm_mma<1><<<dim3(1536/128, MT), 256, SMEM_DYN>>>(act, w1, b_fc1, nullptr, hid, nullptr, NC_A, 1536);
    // 7) FC2 + residual -> out (sequence order)
    gemm_mma<3><<<dim3( 384/128, MT), 256, SMEM_DYN>>>(hid, w2, b_fc2, out, nullptr, xres, NC_H, 384);
}

// round 17
// speedup vs baseline: 1.8240x; 1.1734x over previous
#include <cuda_runtime.h>
#include <cuda_fp16.h>
#include <math.h>
#include <stdint.h>

// ---------------- problem constants ----------------
#define HHs   56
#define NTOK  100352
#define WN    49
#define NC_A  6      // K=384  -> 6 chunks of 64
#define NC_H  24     // K=1536 -> 24 chunks of 64

// ---------------- scratch: chunk-major, pre-swizzled fp16 layouts ----------------
__device__ __align__(1024) __half g_act[(size_t)NC_A * NTOK * 64];
__device__ __align__(1024) __half g_hid[(size_t)NC_H * NTOK * 64];
__device__ __align__(256) __half g_qkv [(size_t)NTOK * 1152];     // fp16 row-major
__device__ __align__(256) float  g_xres[(size_t)NTOK * 384];
// weights: [NC chunks][N][64] single fp16
__device__ __align__(1024) __half g_wq[(size_t)NC_A * 1152 * 64];
__device__ __align__(1024) __half g_wp[(size_t)NC_A *  384 * 64];
__device__ __align__(1024) __half g_w1[(size_t)NC_A * 1536 * 64];
__device__ __align__(1024) __half g_w2[(size_t)NC_H *  384 * 64];

// ---------------- PTX helpers ----------------
__device__ __forceinline__ uint32_t smem_u32(const void* p) {
    uint32_t a;
    asm("{ .reg .u64 t; cvta.to.shared.u64 t, %1; cvt.u32.u64 %0, t; }" : "=r"(a) : "l"(p));
    return a;
}
#define MBARRIER_INIT(mb, c) \
    asm volatile("mbarrier.init.shared.b64 [%0], %1;" :: "r"((uint32_t)(mb)), "r"((uint32_t)(c)) : "memory")
#define MBARRIER_EXPECT_TX(mb, n) \
    asm volatile("mbarrier.arrive.expect_tx.shared.b64 _, [%0], %1;" :: "r"((uint32_t)(mb)), "r"((uint32_t)(n)) : "memory")
#define MBARRIER_ARRIVE(mb) \
    asm volatile("mbarrier.arrive.release.cta.shared.b64 _, [%0];" :: "r"((uint32_t)(mb)) : "memory")
#define MBARRIER_WAIT_PARITY(mb, par) do { \
    uint32_t _m = (uint32_t)(mb), _p = (uint32_t)(par), _d; \
    asm volatile("{\n\t.reg .pred p;\n\t" \
        "mbarrier.try_wait.parity.acquire.cta.shared::cta.b64 p, [%1], %2;\n\t" \
        "selp.b32 %0, 1, 0, p;\n\t}" : "=r"(_d) : "r"(_m), "r"(_p) : "memory"); \
    if (!_d) { \
        asm volatile("{\n\t.reg .pred P1;\n\t" \
            "WL_%=:\n\t" \
            "mbarrier.try_wait.parity.acquire.cta.shared::cta.b64 P1, [%0], %1, 0x989680;\n\t" \
            "@P1 bra.uni WD_%=;\n\t" \
            "bra.uni WL_%=;\n\t" \
            "WD_%=:\n\t}" :: "r"(_m), "r"(_p) : "memory"); \
    } } while (0)
#define BULK_G2S(dst, src, n, mb) \
    asm volatile("cp.async.bulk.shared::cluster.global.mbarrier::complete_tx::bytes [%0], [%1], %2, [%3];" \
        :: "r"((uint32_t)(dst)), "l"(src), "r"((uint32_t)(n)), "r"((uint32_t)(mb)) : "memory")
#define FENCE_ASYNC() asm volatile("fence.proxy.async.shared::cta;" ::: "memory")
#define LDSM_X4(r0, r1, r2, r3, addr) \
    asm volatile("ldmatrix.sync.aligned.m8n8.x4.shared.b16 {%0,%1,%2,%3}, [%4];" \
                 : "=r"(r0), "=r"(r1), "=r"(r2), "=r"(r3) : "r"(addr))

__device__ __forceinline__ void mma16816(float* c, const uint32_t* a, const uint32_t* b) {
    asm volatile("mma.sync.aligned.m16n8k16.row.col.f32.f16.f16.f32 "
        "{%0,%1,%2,%3}, {%4,%5,%6,%7}, {%8,%9}, {%0,%1,%2,%3};"
        : "+f"(c[0]), "+f"(c[1]), "+f"(c[2]), "+f"(c[3])
        : "r"(a[0]), "r"(a[1]), "r"(a[2]), "r"(a[3]), "r"(b[0]), "r"(b[1]));
}

__device__ __forceinline__ uint32_t packh2(float a, float b) {
    __half2 h = __floats2half2_rn(a, b);
    return *reinterpret_cast<uint32_t*>(&h);
}

// fast GELU (tanh form, HW tanh.approx)
__device__ __forceinline__ float gelu_fast(float v) {
    float u = 0.7978845608028654f * (v + 0.044715f * v * v * v);
    float th;
    asm("tanh.approx.f32 %0, %1;" : "=f"(th) : "f"(u));
    return 0.5f * v * (1.0f + th);
}

// window-order row -> sequence row (roll map; same both directions)
__device__ __forceinline__ int win_to_seq(int r) {
    int n  = r % WN;
    int t  = r / WN;
    int wc = t & 7, wr = (t >> 3) & 7, b = t >> 6;
    int n7 = n / 7;
    int h = wr * 7 + n7, w = wc * 7 + (n - n7 * 7);
    int dh = h + 3; if (dh >= HHs) dh -= HHs;
    int dw = w + 3; if (dw >= HHs) dw -= HHs;
    return (b * HHs + dh) * HHs + dw;
}

// fp16 store of 2 adjacent cols into chunk-major swizzled layout (k even)
__device__ __forceinline__ void h_store2(__half* base, int rows, int tok, int k,
                                         float v0, float v1) {
    int ch  = k >> 6;
    int idx = ((((k >> 3) & 7) ^ (tok & 7)) << 3) + (k & 7);
    *(__half2*)(base + ((size_t)ch * rows + tok) * 64 + idx) = __floats2half2_rn(v0, v1);
}

// ---------------- merged weight prep: all 4 weights in one launch ----------------
__global__ void wprep_all(const float* __restrict__ Wq, const float* __restrict__ Wp,
                          const float* __restrict__ W1, const float* __restrict__ W2,
                          __half* __restrict__ Oq, __half* __restrict__ Op,
                          __half* __restrict__ O1, __half* __restrict__ O2)
{
    __shared__ float t[32][33];
    int b = blockIdx.x;
    const float* W; __half* O; int K, N, nx;
    if (b < 432)       { W = Wq; O = Oq; K = 384;  N = 1152; nx = 36; }
    else if (b < 576)  { b -= 432;  W = Wp; O = Op; K = 384;  N = 384;  nx = 12; }
    else if (b < 1152) { b -= 576;  W = W1; O = O1; K = 384;  N = 1536; nx = 48; }
    else               { b -= 1152; W = W2; O = O2; K = 1536; N = 384;  nx = 12; }
    (void)K;
    int nb = (b % nx) * 32, kb = (b / nx) * 32;
    for (int i = threadIdx.y; i < 32; i += 8)
        t[i][threadIdx.x] = W[(size_t)(kb + i) * N + nb + threadIdx.x];
    __syncthreads();
    for (int i = threadIdx.y; i < 32; i += 8) {
        float v = t[threadIdx.x][i];
        int k = kb + threadIdx.x, n = nb + i;
        int ch  = k >> 6;
        int idx = ((((k >> 3) & 7) ^ (n & 7)) << 3) + (k & 7);
        O[((size_t)ch * N + n) * 64 + idx] = __float2half_rn(v);
    }
}

// ---------------- LayerNorm -> chunked fp16 (one warp per token) ----------------
template<bool PERM>
__global__ void ln_kernel(const float* __restrict__ X, const float* __restrict__ G,
                          const float* __restrict__ Bv, __half* __restrict__ Y)
{
    int gw   = (blockIdx.x * blockDim.x + threadIdx.x) >> 5;
    int lane = threadIdx.x & 31;
    if (gw >= NTOK) return;
    int src = PERM ? win_to_seq(gw) : gw;
    const float4* xr = (const float4*)(X + (size_t)src * 384);
    float4 a = xr[lane], b = xr[32 + lane], c = xr[64 + lane];
    float s = a.x+a.y+a.z+a.w + b.x+b.y+b.z+b.w + c.x+c.y+c.z+c.w;
    float q = a.x*a.x+a.y*a.y+a.z*a.z+a.w*a.w
            + b.x*b.x+b.y*b.y+b.z*b.z+b.w*b.w
            + c.x*c.x+c.y*c.y+c.z*c.z+c.w*c.w;
    #pragma unroll
    for (int o = 16; o; o >>= 1) {
        s += __shfl_xor_sync(0xffffffffu, s, o);
        q += __shfl_xor_sync(0xffffffffu, q, o);
    }
    float mu  = s * (1.0f / 384.0f);
    float var = q * (1.0f / 384.0f) - mu * mu;
    float rs  = rsqrtf(var + 1e-5f);
    const float4* gg = (const float4*)G;
    const float4* bb = (const float4*)Bv;
    #pragma unroll
    for (int seg = 0; seg < 3; seg++) {
        float4 v  = (seg == 0) ? a : (seg == 1) ? b : c;
        float4 g4 = gg[seg * 32 + lane];
        float4 b4 = bb[seg * 32 + lane];
        int k0 = seg * 128 + lane * 4;
        float w0 = (v.x - mu) * rs * g4.x + b4.x;
        float w1 = (v.y - mu) * rs * g4.y + b4.y;
        float w2 = (v.z - mu) * rs * g4.z + b4.z;
        float w3 = (v.w - mu) * rs * g4.w + b4.w;
        h_store2(Y, NTOK, gw, k0,     w0, w1);
        h_store2(Y, NTOK, gw, k0 + 2, w2, w3);
    }
}

// ---------------- attention via mma.sync: one warp per (window, head) ----------------
// per-warp smem: Q 64x(80B), K 64x(80B), Vt 32x(144B)
#define AQ_OFF 0
#define AK_OFF 5120
#define AV_OFF 10240
#define AW_BYTES 14848
#define A_SMEM (AW_BYTES * 4)

__global__ __launch_bounds__(128)
void attn_mma(const __half* __restrict__ qkv, __half* __restrict__ O)
{
    extern __shared__ __align__(1024) char smA[];
    int tid = threadIdx.x, lane = tid & 31, w = tid >> 5;
    int gw = blockIdx.x * 4 + w;
    int win = gw / 12, head = gw - win * 12;
    char* wp = smA + w * AW_BYTES;
    uint32_t wb = smem_u32(wp);

    // zero warp region (covers Q/K rows 49..63 and Vt cols 49..63)
    for (int i = lane; i < AW_BYTES / 16; i += 32)
        *(uint4*)(wp + i * 16) = make_uint4(0, 0, 0, 0);
    __syncwarp();

    const __half* g = qkv + (size_t)win * WN * 1152 + head * 32;
    const __half2 sc2 = __floats2half2_rn(0.17677669529663687f, 0.17677669529663687f);

    for (int i = lane; i < 49 * 4; i += 32) {
        int r = i >> 2, c = i & 3;
        uint4 qv = *(const uint4*)(g + (size_t)r * 1152 + c * 8);
        __half2* qp = (__half2*)&qv;
        #pragma unroll
        for (int u = 0; u < 4; u++) qp[u] = __hmul2(qp[u], sc2);
        *(uint4*)(wp + AQ_OFF + r * 80 + c * 16) = qv;
        *(uint4*)(wp + AK_OFF + r * 80 + c * 16) =
            *(const uint4*)(g + (size_t)r * 1152 + 384 + c * 8);
    }
    __half* vt = (__half*)(wp + AV_OFF);
    for (int i = lane; i < 49 * 16; i += 32) {
        int p = i >> 4, dp = i & 15;
        __half2 v = *(const __half2*)(g + (size_t)p * 1152 + 768 + dp * 2);
        vt[(2 * dp) * 72 + p]     = __low2half(v);
        vt[(2 * dp + 1) * 72 + p] = __high2half(v);
    }
    __syncwarp();

    int lr = lane >> 2, c0 = 2 * (lane & 3);
    int tokb = win * WN, kcol = head * 32;

    for (int mt = 0; mt < 4; mt++) {
        // Q A-fragments for rows mt*16..+15, k-tiles 0..1
        uint32_t qa[2][4];
        #pragma unroll
        for (int kt = 0; kt < 2; kt++)
            LDSM_X4(qa[kt][0], qa[kt][1], qa[kt][2], qa[kt][3],
                    wb + AQ_OFF + (uint32_t)(mt * 16 + (lane & 15)) * 80
                       + kt * 32 + ((lane >> 4) << 4));

        float s[8][4];
        #pragma unroll
        for (int nt = 0; nt < 8; nt++)
            #pragma unroll
            for (int u = 0; u < 4; u++) s[nt][u] = 0.0f;

        #pragma unroll
        for (int g2 = 0; g2 < 4; g2++)
            #pragma unroll
            for (int kt = 0; kt < 2; kt++) {
                uint32_t r0, r1, r2, r3;
                LDSM_X4(r0, r1, r2, r3,
                        wb + AK_OFF + (uint32_t)(g2 * 16 + (lane & 15)) * 80
                           + kt * 32 + ((lane >> 4) << 4));
                uint32_t b0[2] = {r0, r2}, b1[2] = {r1, r3};
                mma16816(s[2 * g2],     qa[kt], b0);
                mma16816(s[2 * g2 + 1], qa[kt], b1);
            }

        // mask cols >= 49
        if ((lane & 3) != 0) { s[6][0] = -1e30f; s[6][2] = -1e30f; }
        s[6][1] = -1e30f; s[6][3] = -1e30f;
        s[7][0] = s[7][1] = s[7][2] = s[7][3] = -1e30f;

        float mx0 = -1e30f, mx1 = -1e30f;
        #pragma unroll
        for (int nt = 0; nt < 8; nt++) {
            mx0 = fmaxf(mx0, fmaxf(s[nt][0], s[nt][1]));
            mx1 = fmaxf(mx1, fmaxf(s[nt][2], s[nt][3]));
        }
        #pragma unroll
        for (int o = 1; o <= 2; o <<= 1) {
            mx0 = fmaxf(mx0, __shfl_xor_sync(0xffffffffu, mx0, o));
            mx1 = fmaxf(mx1, __shfl_xor_sync(0xffffffffu, mx1, o));
        }
        float sum0 = 0.0f, sum1 = 0.0f;
        #pragma unroll
        for (int nt = 0; nt < 8; nt++) {
            s[nt][0] = __expf(s[nt][0] - mx0); sum0 += s[nt][0];
            s[nt][1] = __expf(s[nt][1] - mx0); sum0 += s[nt][1];
            s[nt][2] = __expf(s[nt][2] - mx1); sum1 += s[nt][2];
            s[nt][3] = __expf(s[nt][3] - mx1); sum1 += s[nt][3];
        }
        #pragma unroll
        for (int o = 1; o <= 2; o <<= 1) {
            sum0 += __shfl_xor_sync(0xffffffffu, sum0, o);
            sum1 += __shfl_xor_sync(0xffffffffu, sum1, o);
        }

        // P (exp weights) -> A fragments (C->A register identity)
        uint32_t pa[4][4];
        #pragma unroll
        for (int kt = 0; kt < 4; kt++) {
            pa[kt][0] = packh2(s[2*kt][0],   s[2*kt][1]);
            pa[kt][1] = packh2(s[2*kt][2],   s[2*kt][3]);
            pa[kt][2] = packh2(s[2*kt+1][0], s[2*kt+1][1]);
            pa[kt][3] = packh2(s[2*kt+1][2], s[2*kt+1][3]);
        }

        float o4[4][4];
        #pragma unroll
        for (int nt = 0; nt < 4; nt++)
            #pragma unroll
            for (int u = 0; u < 4; u++) o4[nt][u] = 0.0f;

        #pragma unroll
        for (int g2 = 0; g2 < 2; g2++)
            #pragma unroll
            for (int kt = 0; kt < 4; kt++) {
                uint32_t r0, r1, r2, r3;
                LDSM_X4(r0, r1, r2, r3,
                        wb + AV_OFF + (uint32_t)(g2 * 16 + (lane & 15)) * 144
                           + kt * 32 + ((lane >> 4) << 4));
                uint32_t b0[2] = {r0, r2}, b1[2] = {r1, r3};
                mma16816(o4[2 * g2],     pa[kt], b0);
                mma16816(o4[2 * g2 + 1], pa[kt], b1);
            }

        float inv0 = 1.0f / sum0, inv1 = 1.0f / sum1;
        int r = mt * 16 + lr;
        if (r < WN) {
            #pragma unroll
            for (int nt = 0; nt < 4; nt++)
                h_store2(O, NTOK, tokb + r, kcol + nt * 8 + c0,
                         o4[nt][0] * inv0, o4[nt][1] * inv0);
        }
        if (r + 8 < WN) {
            #pragma unroll
            for (int nt = 0; nt < 4; nt++)
                h_store2(O, NTOK, tokb + r + 8, kcol + nt * 8 + c0,
                         o4[nt][2] * inv1, o4[nt][3] * inv1);
        }
    }
}

// ---------------- fp16 GEMM: 128x128 CTA, 3 stages, rotating producer + proxy fence ----------------
#define STAGES 3
#define STG_BYTES 32768
#define MBAR_OFF  98304
#define SMEM_DYN  (98304 + 64)

// EPI 0: qkv fp16   1: gelu -> chunked fp16   2: scatter+resid fp32   3: resid fp32
template<int EPI>
__global__ __launch_bounds__(256, 2)
void gemm_mma(const __half* __restrict__ A, const __half* __restrict__ B,
              const float* __restrict__ bias, float* __restrict__ Co,
              __half* __restrict__ O2, const float* __restrict__ resid,
              int NC, int Nn)
{
    extern __shared__ __align__(1024) char sm[];
    uint32_t sb = smem_u32(sm);
    int tid = threadIdx.x, lane = tid & 31, wid = tid >> 5;
    int wm = wid & 1, wn = wid >> 1;
    int m0 = blockIdx.y * 128, n0 = blockIdx.x * 128;

    if (tid == 0) {
        #pragma unroll
        for (int s = 0; s < STAGES; s++) {
            MBARRIER_INIT(sb + MBAR_OFF + s * 8, 1);
            MBARRIER_INIT(sb + MBAR_OFF + 24 + s * 8, 8);
        }
        FENCE_ASYNC();
    }
    __syncthreads();

    auto issue = [&](int j) {
        const char* asrc = (const char*)A + ((size_t)j * NTOK + m0) * 128;
        const char* bsrc = (const char*)B + ((size_t)j * Nn   + n0) * 128;
        int s = j % STAGES;
        uint32_t dst = sb + s * STG_BYTES;
        uint32_t mb  = sb + MBAR_OFF + s * 8;
        MBARRIER_EXPECT_TX(mb, 32768);
        BULK_G2S(dst,         asrc, 16384, mb);
        BULK_G2S(dst + 16384, bsrc, 16384, mb);
    };
    if (tid == 0) { issue(0); issue(1); issue(2); }

    float acc[4][4][4];
    #pragma unroll
    for (int i = 0; i < 4; i++)
        #pragma unroll
        for (int j = 0; j < 4; j++)
            #pragma unroll
            for (int u = 0; u < 4; u++) acc[i][j][u] = 0.0f;

    for (int i = 0; i < NC; i++) {
        int s = i % STAGES;
        MBARRIER_WAIT_PARITY(sb + MBAR_OFF + s * 8, (i / STAGES) & 1);

        uint32_t As = sb + s * STG_BYTES;
        uint32_t Bs = As + 16384;
        #pragma unroll
        for (int kk = 0; kk < 4; kk++) {
            int ch = kk * 2 + (lane >> 4);
            uint32_t b[4][2];
            #pragma unroll
            for (int j2 = 0; j2 < 2; j2++) {
                int row = wn * 32 + j2 * 16 + (lane & 15);
                uint32_t r0, r1, r2, r3;
                LDSM_X4(r0, r1, r2, r3,
                        Bs + (uint32_t)row * 128 + (uint32_t)((ch ^ (row & 7)) << 4));
                b[2*j2][0] = r0; b[2*j2][1] = r2;
                b[2*j2+1][0] = r1; b[2*j2+1][1] = r3;
            }
            #pragma unroll
            for (int ii = 0; ii < 4; ii++) {
                int row = wm * 64 + ii * 16 + (lane & 15);
                uint32_t a[4];
                LDSM_X4(a[0], a[1], a[2], a[3],
                        As + (uint32_t)row * 128 + (uint32_t)((ch ^ (row & 7)) << 4));
                #pragma unroll
                for (int j = 0; j < 4; j++) mma16816(acc[ii][j], a, b[j]);
            }
        }
        __syncwarp();
        if (lane == 0) MBARRIER_ARRIVE(sb + MBAR_OFF + 24 + s * 8);
        if (i + STAGES < NC && wid == (i & 7)) {
            if (lane == 0) {
                MBARRIER_WAIT_PARITY(sb + MBAR_OFF + 24 + s * 8, (i / STAGES) & 1);
                FENCE_ASYNC();
                issue(i + STAGES);
            }
            __syncwarp();
        }
    }

    // ---- direct register epilogue ----
    int cbase = n0 + wn * 32 + 2 * (lane & 3);
    float2 bv[4];
    #pragma unroll
    for (int j = 0; j < 4; j++) bv[j] = *(const float2*)(bias + cbase + j * 8);
    #pragma unroll
    for (int ii = 0; ii < 4; ii++) {
        #pragma unroll
        for (int half = 0; half < 2; half++) {
            int grow = m0 + wm * 64 + ii * 16 + (lane >> 2) + half * 8;
            size_t orow;
            const float* rp = nullptr;
            if (EPI == 2) { orow = (size_t)win_to_seq(grow) * Nn; rp = resid + orow; }
            else if (EPI == 3) { orow = (size_t)grow * Nn; rp = resid + orow; }
            else orow = (size_t)grow * Nn;
            #pragma unroll
            for (int j = 0; j < 4; j++) {
                int gcol = cbase + j * 8;
                float v0 = acc[ii][j][2*half]   + bv[j].x;
                float v1 = acc[ii][j][2*half+1] + bv[j].y;
                if (EPI == 0) {
                    *(__half2*)(O2 + (size_t)grow * Nn + gcol) = __floats2half2_rn(v0, v1);
                } else if (EPI == 1) {
                    v0 = gelu_fast(v0);
                    v1 = gelu_fast(v1);
                    h_store2(O2, NTOK, grow, gcol, v0, v1);
                } else {
                    float2 rr = *(const float2*)(rp + gcol);
                    *(float2*)(Co + orow + gcol) = make_float2(v0 + rr.x, v1 + rr.y);
                }
            }
        }
    }
}

// ---------------- launcher ----------------
extern "C" void kernel_launch(void* const* d_in, const int* in_sizes, int n_in,
                              void* d_out, int out_size)
{
    const float* x      = (const float*)d_in[0];
    const float* ln1_g  = (const float*)d_in[1];
    const float* ln1_b  = (const float*)d_in[2];
    const float* w_qkv  = (const float*)d_in[3];
    const float* b_qkv  = (const float*)d_in[4];
    const float* w_proj = (const float*)d_in[5];
    const float* b_proj = (const float*)d_in[6];
    const float* ln2_g  = (const float*)d_in[7];
    const float* ln2_b  = (const float*)d_in[8];
    const float* w_fc1  = (const float*)d_in[9];
    const float* b_fc1  = (const float*)d_in[10];
    const float* w_fc2  = (const float*)d_in[11];
    const float* b_fc2  = (const float*)d_in[12];
    float* out = (float*)d_out;

    __half *act, *hid, *qkv, *wq, *wp, *w1, *w2;
    float *xres;
    cudaGetSymbolAddress((void**)&act,  g_act);
    cudaGetSymbolAddress((void**)&hid,  g_hid);
    cudaGetSymbolAddress((void**)&qkv,  g_qkv);
    cudaGetSymbolAddress((void**)&xres, g_xres);
    cudaGetSymbolAddress((void**)&wq,   g_wq);
    cudaGetSymbolAddress((void**)&wp,   g_wp);
    cudaGetSymbolAddress((void**)&w1,   g_w1);
    cudaGetSymbolAddress((void**)&w2,   g_w2);

    cudaFuncSetAttribute(gemm_mma<0>, cudaFuncAttributeMaxDynamicSharedMemorySize, SMEM_DYN);
    cudaFuncSetAttribute(gemm_mma<1>, cudaFuncAttributeMaxDynamicSharedMemorySize, SMEM_DYN);
    cudaFuncSetAttribute(gemm_mma<2>, cudaFuncAttributeMaxDynamicSharedMemorySize, SMEM_DYN);
    cudaFuncSetAttribute(gemm_mma<3>, cudaFuncAttributeMaxDynamicSharedMemorySize, SMEM_DYN);
    cudaFuncSetAttribute(attn_mma,    cudaFuncAttributeMaxDynamicSharedMemorySize, A_SMEM);

    // weight prep (single merged launch)
    wprep_all<<<1728, dim3(32, 8)>>>(w_qkv, w_proj, w_fc1, w_fc2, wq, wp, w1, w2);

    const int MT = NTOK / 128;   // 784

    // 1) LN1 + roll + window partition -> act (window order)
    ln_kernel<true><<<NTOK / 8, 256>>>(x, ln1_g, ln1_b, act);
    // 2) QKV -> fp16
    gemm_mma<0><<<dim3(1152/128, MT), 256, SMEM_DYN>>>(act, wq, b_qkv, nullptr, qkv, nullptr, NC_A, 1152);
    // 3) attention (tensor cores) -> act (window order)
    attn_mma<<<(2048 * 12) / 4, 128, A_SMEM>>>(qkv, act);
    // 4) proj + reverse/roll + residual -> xres (sequence order)
    gemm_mma<2><<<dim3( 384/128, MT), 256, SMEM_DYN>>>(act, wp, b_proj, xres, nullptr, x, NC_A, 384);
    // 5) LN2 -> act (sequence order)
    ln_kernel<false><<<NTOK / 8, 256>>>(xres, ln2_g, ln2_b, act);
    // 6) FC1 + fast GELU -> hid (sequence order)
    gemm_mma<1><<<dim3(1536/128, MT), 256, SMEM_DYN>>>(act, w1, b_fc1, nullptr, hid, nullptr, NC_A, 1536);
    // 7) FC2 + residual -> out (sequence order)
    gemm_mma<3><<<dim3( 384/128, MT), 256, SMEM_DYN>>>(hid, w2, b_fc2, out, nullptr, xres, NC_H, 384);
}